// round 1
// baseline (speedup 1.0000x reference)
#include <cuda_runtime.h>
#include <cuda_bf16.h>
#include <math.h>

// Problem constants
#define BATCH 4
#define SEQ   4096
#define DIM   1024           // H_DIM == HEAD_SIZE
#define MTOT  (BATCH * SEQ)  // 16384

// GEMM tiling
#define BM 128
#define BN 128
#define BKT 16
#define TM 8
#define TN 8
#define NTHREADS 256

// Scratch (allocation-free rule: __device__ globals)
__device__ float g_q[BATCH * SEQ * DIM];
__device__ float g_k[BATCH * SEQ * DIM];
__device__ float g_v[BATCH * SEQ * DIM];
__device__ float g_s[(size_t)BATCH * SEQ * SEQ];   // 256 MB scores/weights

// ---------------------------------------------------------------------------
// Kernel 1: fused QKV projection.  Y = x @ W + b
// x: [MTOT, DIM] row-major.  W: [DIM, DIM] row-major.  blockIdx.z selects q/k/v.
// grid: (DIM/BN, MTOT/BM, 3)
// ---------------------------------------------------------------------------
__global__ __launch_bounds__(NTHREADS)
void qkv_gemm_kernel(const float* __restrict__ x,
                     const float* __restrict__ Wq, const float* __restrict__ bq,
                     const float* __restrict__ Wk, const float* __restrict__ bk,
                     const float* __restrict__ Wv, const float* __restrict__ bv)
{
    const float* W;
    const float* bias;
    float* out;
    if (blockIdx.z == 0)      { W = Wq; bias = bq; out = g_q; }
    else if (blockIdx.z == 1) { W = Wk; bias = bk; out = g_k; }
    else                      { W = Wv; bias = bv; out = g_v; }

    const int row0 = blockIdx.y * BM;
    const int col0 = blockIdx.x * BN;
    const int lda = DIM, ldb = DIM;

    __shared__ float As[BKT][BM];
    __shared__ float Bs[BKT][BN];

    const int tid = threadIdx.x;
    const int tx = tid & 15;
    const int ty = tid >> 4;

    float acc[TM][TN];
#pragma unroll
    for (int i = 0; i < TM; i++)
#pragma unroll
        for (int j = 0; j < TN; j++) acc[i][j] = 0.0f;

    const float* Abase = x + (size_t)row0 * lda;
    const float* Bbase = W + col0;

    for (int k0 = 0; k0 < DIM; k0 += BKT) {
        // Load A tile (transpose into As[k][m])
#pragma unroll
        for (int i = 0; i < 2; i++) {
            int f = tid * 2 + i;
            int r = f >> 2, c4 = f & 3;
            float4 v = *(const float4*)(Abase + (size_t)r * lda + k0 + c4 * 4);
            As[c4 * 4 + 0][r] = v.x;
            As[c4 * 4 + 1][r] = v.y;
            As[c4 * 4 + 2][r] = v.z;
            As[c4 * 4 + 3][r] = v.w;
        }
        // Load B tile (direct)
#pragma unroll
        for (int i = 0; i < 2; i++) {
            int f = tid * 2 + i;
            int r = f >> 5, c4 = f & 31;
            *(float4*)(&Bs[r][c4 * 4]) =
                *(const float4*)(Bbase + (size_t)(k0 + r) * ldb + c4 * 4);
        }
        __syncthreads();

#pragma unroll
        for (int kk = 0; kk < BKT; kk++) {
            float a[TM], b[TN];
            *(float4*)(a)     = *(const float4*)(&As[kk][ty * 8]);
            *(float4*)(a + 4) = *(const float4*)(&As[kk][ty * 8 + 4]);
            *(float4*)(b)     = *(const float4*)(&Bs[kk][tx * 8]);
            *(float4*)(b + 4) = *(const float4*)(&Bs[kk][tx * 8 + 4]);
#pragma unroll
            for (int i = 0; i < TM; i++)
#pragma unroll
                for (int j = 0; j < TN; j++)
                    acc[i][j] = fmaf(a[i], b[j], acc[i][j]);
        }
        __syncthreads();
    }

    // Epilogue with bias
#pragma unroll
    for (int i = 0; i < TM; i++) {
        int row = row0 + ty * 8 + i;
        int col = col0 + tx * 8;
        float4 o0, o1;
        o0.x = acc[i][0] + bias[col + 0];
        o0.y = acc[i][1] + bias[col + 1];
        o0.z = acc[i][2] + bias[col + 2];
        o0.w = acc[i][3] + bias[col + 3];
        o1.x = acc[i][4] + bias[col + 4];
        o1.y = acc[i][5] + bias[col + 5];
        o1.z = acc[i][6] + bias[col + 6];
        o1.w = acc[i][7] + bias[col + 7];
        *(float4*)(out + (size_t)row * DIM + col)     = o0;
        *(float4*)(out + (size_t)row * DIM + col + 4) = o1;
    }
}

// ---------------------------------------------------------------------------
// Kernel 2: causal scores  s[b][i][j] = q[b][i] . k[b][j]   (NT GEMM)
// grid: (SEQ/BN, SEQ/BM, BATCH). Blocks fully above the diagonal exit early.
// No masking here: softmax only reads j<=i and zero-fills the rest.
// ---------------------------------------------------------------------------
__global__ __launch_bounds__(NTHREADS)
void scores_gemm_kernel()
{
    const int row0 = blockIdx.y * BM;
    const int col0 = blockIdx.x * BN;
    if (col0 > row0 + BM - 1) return;   // strictly above diagonal

    const int b = blockIdx.z;
    const float* qb = g_q + (size_t)b * SEQ * DIM;
    const float* kb = g_k + (size_t)b * SEQ * DIM;
    float* sb = g_s + (size_t)b * SEQ * SEQ;

    __shared__ float As[BKT][BM];
    __shared__ float Bs[BKT][BN];

    const int tid = threadIdx.x;
    const int tx = tid & 15;
    const int ty = tid >> 4;

    float acc[TM][TN];
#pragma unroll
    for (int i = 0; i < TM; i++)
#pragma unroll
        for (int j = 0; j < TN; j++) acc[i][j] = 0.0f;

    const float* Abase = qb + (size_t)row0 * DIM;
    const float* Bbase = kb + (size_t)col0 * DIM;

    for (int k0 = 0; k0 < DIM; k0 += BKT) {
#pragma unroll
        for (int i = 0; i < 2; i++) {
            int f = tid * 2 + i;
            int r = f >> 2, c4 = f & 3;
            float4 v = *(const float4*)(Abase + (size_t)r * DIM + k0 + c4 * 4);
            As[c4 * 4 + 0][r] = v.x;
            As[c4 * 4 + 1][r] = v.y;
            As[c4 * 4 + 2][r] = v.z;
            As[c4 * 4 + 3][r] = v.w;
        }
#pragma unroll
        for (int i = 0; i < 2; i++) {
            int f = tid * 2 + i;
            int r = f >> 2, c4 = f & 3;
            float4 v = *(const float4*)(Bbase + (size_t)r * DIM + k0 + c4 * 4);
            Bs[c4 * 4 + 0][r] = v.x;
            Bs[c4 * 4 + 1][r] = v.y;
            Bs[c4 * 4 + 2][r] = v.z;
            Bs[c4 * 4 + 3][r] = v.w;
        }
        __syncthreads();

#pragma unroll
        for (int kk = 0; kk < BKT; kk++) {
            float a[TM], bb[TN];
            *(float4*)(a)      = *(const float4*)(&As[kk][ty * 8]);
            *(float4*)(a + 4)  = *(const float4*)(&As[kk][ty * 8 + 4]);
            *(float4*)(bb)     = *(const float4*)(&Bs[kk][tx * 8]);
            *(float4*)(bb + 4) = *(const float4*)(&Bs[kk][tx * 8 + 4]);
#pragma unroll
            for (int i = 0; i < TM; i++)
#pragma unroll
                for (int j = 0; j < TN; j++)
                    acc[i][j] = fmaf(a[i], bb[j], acc[i][j]);
        }
        __syncthreads();
    }

#pragma unroll
    for (int i = 0; i < TM; i++) {
        int row = row0 + ty * 8 + i;
        int col = col0 + tx * 8;
        *(float4*)(sb + (size_t)row * SEQ + col)     = *(float4*)(&acc[i][0]);
        *(float4*)(sb + (size_t)row * SEQ + col + 4) = *(float4*)(&acc[i][4]);
    }
}

// ---------------------------------------------------------------------------
// Kernel 3: causal row softmax in-place on g_s.
// w[i][j] = softmax_j<=i(s[i][j] / 32); zero-fill j in (i, roundup128(i+1))
// so the PV GEMM can read full 128-row K tiles.
// grid: (SEQ, BATCH), 256 threads.
// ---------------------------------------------------------------------------
__global__ __launch_bounds__(NTHREADS)
void softmax_kernel()
{
    const int j = blockIdx.x;          // query row
    const int b = blockIdx.y;
    float* row = g_s + ((size_t)b * SEQ + j) * SEQ;
    const int n = j + 1;

    __shared__ float red[NTHREADS];
    const int tid = threadIdx.x;
    const float scale = 0.03125f;      // 1/sqrt(1024)

    // pass 1: max
    float m = -INFINITY;
    for (int k = tid; k < n; k += NTHREADS) m = fmaxf(m, row[k]);
    red[tid] = m;
    __syncthreads();
    for (int s = NTHREADS / 2; s > 0; s >>= 1) {
        if (tid < s) red[tid] = fmaxf(red[tid], red[tid + s]);
        __syncthreads();
    }
    m = red[0];
    __syncthreads();

    // pass 2: exp + sum (store exp in place)
    float sum = 0.0f;
    for (int k = tid; k < n; k += NTHREADS) {
        float e = __expf((row[k] - m) * scale);
        row[k] = e;
        sum += e;
    }
    red[tid] = sum;
    __syncthreads();
    for (int s = NTHREADS / 2; s > 0; s >>= 1) {
        if (tid < s) red[tid] += red[tid + s];
        __syncthreads();
    }
    const float rsum = 1.0f / red[0];
    __syncthreads();

    // pass 3: normalize + zero-fill to the 128-padded boundary
    for (int k = tid; k < n; k += NTHREADS) row[k] *= rsum;
    const int npad = ((j >> 7) + 1) << 7;
    for (int k = n + tid; k < npad; k += NTHREADS) row[k] = 0.0f;
}

// ---------------------------------------------------------------------------
// Kernel 4: out = w @ v, with K loop truncated at the causal boundary.
// grid: (DIM/BN, SEQ/BM, BATCH)
// ---------------------------------------------------------------------------
__global__ __launch_bounds__(NTHREADS)
void pv_gemm_kernel(float* __restrict__ out_all)
{
    const int row0 = blockIdx.y * BM;
    const int col0 = blockIdx.x * BN;
    const int b = blockIdx.z;

    const float* wb = g_s + (size_t)b * SEQ * SEQ;
    const float* vb = g_v + (size_t)b * SEQ * DIM;
    float* out = out_all + (size_t)b * SEQ * DIM;

    __shared__ float As[BKT][BM];
    __shared__ float Bs[BKT][BN];

    const int tid = threadIdx.x;
    const int tx = tid & 15;
    const int ty = tid >> 4;

    float acc[TM][TN];
#pragma unroll
    for (int i = 0; i < TM; i++)
#pragma unroll
        for (int j = 0; j < TN; j++) acc[i][j] = 0.0f;

    const float* Abase = wb + (size_t)row0 * SEQ;
    const float* Bbase = vb + col0;

    const int Klim = row0 + BM;   // causal: weights beyond this are zero-filled

    for (int k0 = 0; k0 < Klim; k0 += BKT) {
#pragma unroll
        for (int i = 0; i < 2; i++) {
            int f = tid * 2 + i;
            int r = f >> 2, c4 = f & 3;
            float4 v = *(const float4*)(Abase + (size_t)r * SEQ + k0 + c4 * 4);
            As[c4 * 4 + 0][r] = v.x;
            As[c4 * 4 + 1][r] = v.y;
            As[c4 * 4 + 2][r] = v.z;
            As[c4 * 4 + 3][r] = v.w;
        }
#pragma unroll
        for (int i = 0; i < 2; i++) {
            int f = tid * 2 + i;
            int r = f >> 5, c4 = f & 31;
            *(float4*)(&Bs[r][c4 * 4]) =
                *(const float4*)(Bbase + (size_t)(k0 + r) * DIM + c4 * 4);
        }
        __syncthreads();

#pragma unroll
        for (int kk = 0; kk < BKT; kk++) {
            float a[TM], bb[TN];
            *(float4*)(a)      = *(const float4*)(&As[kk][ty * 8]);
            *(float4*)(a + 4)  = *(const float4*)(&As[kk][ty * 8 + 4]);
            *(float4*)(bb)     = *(const float4*)(&Bs[kk][tx * 8]);
            *(float4*)(bb + 4) = *(const float4*)(&Bs[kk][tx * 8 + 4]);
#pragma unroll
            for (int i = 0; i < TM; i++)
#pragma unroll
                for (int j = 0; j < TN; j++)
                    acc[i][j] = fmaf(a[i], bb[j], acc[i][j]);
        }
        __syncthreads();
    }

#pragma unroll
    for (int i = 0; i < TM; i++) {
        int row = row0 + ty * 8 + i;
        int col = col0 + tx * 8;
        *(float4*)(out + (size_t)row * DIM + col)     = *(float4*)(&acc[i][0]);
        *(float4*)(out + (size_t)row * DIM + col + 4) = *(float4*)(&acc[i][4]);
    }
}

// ---------------------------------------------------------------------------
extern "C" void kernel_launch(void* const* d_in, const int* in_sizes, int n_in,
                              void* d_out, int out_size)
{
    const float* x  = (const float*)d_in[0];
    const float* Wq = (const float*)d_in[1];
    const float* bq = (const float*)d_in[2];
    const float* Wk = (const float*)d_in[3];
    const float* bk = (const float*)d_in[4];
    const float* Wv = (const float*)d_in[5];
    const float* bv = (const float*)d_in[6];
    float* out = (float*)d_out;

    // 1. QKV projections
    {
        dim3 grid(DIM / BN, MTOT / BM, 3);
        qkv_gemm_kernel<<<grid, NTHREADS>>>(x, Wq, bq, Wk, bk, Wv, bv);
    }
    // 2. Causal scores (NT)
    {
        dim3 grid(SEQ / BN, SEQ / BM, BATCH);
        scores_gemm_kernel<<<grid, NTHREADS>>>();
    }
    // 3. Softmax
    {
        dim3 grid(SEQ, BATCH);
        softmax_kernel<<<grid, NTHREADS>>>();
    }
    // 4. PV
    {
        dim3 grid(DIM / BN, SEQ / BM, BATCH);
        pv_gemm_kernel<<<grid, NTHREADS>>>(out);
    }
}

// round 2
// speedup vs baseline: 3.4576x; 3.4576x over previous
#include <cuda_runtime.h>
#include <cuda_bf16.h>
#include <math.h>
#include <stdint.h>

// Problem constants
#define BATCH 4
#define SEQ   4096
#define DIM   1024
#define MTOT  (BATCH * SEQ)   // 16384

// Tiling
#define BM 128
#define BN 128
#define BK 32
#define NTHREADS 256

// Smem strides (floats), chosen for conflict-free fragment loads
#define AS_STRIDE 36            // A tile [BM][36]   (bank = 4*g + q, distinct)
#define BNT_STRIDE 36           // B^T tile [BN][36] (scores: B global is [N,K])
#define BNN_STRIDE 136          // B tile [BK][136]  (QKV/PV: B global is [K,N]; bank = 8*q + g)

#define AS_ELEMS  (BM * AS_STRIDE)    // 4608
#define BNT_ELEMS (BN * BNT_STRIDE)   // 4608
#define BNN_ELEMS (BK * BNN_STRIDE)   // 4352

#define SMEM_NT_BYTES (2 * (AS_ELEMS + BNT_ELEMS) * 4)   // 73728
#define SMEM_NN_BYTES (2 * (AS_ELEMS + BNN_ELEMS) * 4)   // 71680

// Scratch (__device__ globals: allocation-free rule)
__device__ float g_q[BATCH * SEQ * DIM];
__device__ float g_k[BATCH * SEQ * DIM];
__device__ float g_v[BATCH * SEQ * DIM];
__device__ float g_s[(size_t)BATCH * SEQ * SEQ];   // 256 MB scores/weights

// ---------------------------------------------------------------------------
// Helpers
// ---------------------------------------------------------------------------
__device__ __forceinline__ uint32_t f2tf(float f) {
    uint32_t u;
    asm("cvt.rna.tf32.f32 %0, %1;" : "=r"(u) : "f"(f));
    return u;
}

__device__ __forceinline__ void mma8(float* d, const uint32_t* a, const uint32_t* b) {
    asm volatile(
        "mma.sync.aligned.m16n8k8.row.col.f32.tf32.tf32.f32 "
        "{%0,%1,%2,%3}, {%4,%5,%6,%7}, {%8,%9}, {%0,%1,%2,%3};\n"
        : "+f"(d[0]), "+f"(d[1]), "+f"(d[2]), "+f"(d[3])
        : "r"(a[0]), "r"(a[1]), "r"(a[2]), "r"(a[3]), "r"(b[0]), "r"(b[1]));
}

__device__ __forceinline__ void cp16(uint32_t dst, const void* src) {
    asm volatile("cp.async.cg.shared.global [%0], [%1], 16;\n" :: "r"(dst), "l"(src));
}
#define CP_COMMIT() asm volatile("cp.async.commit_group;\n")
#define CP_WAIT1()  asm volatile("cp.async.wait_group 1;\n")
#define CP_WAIT0()  asm volatile("cp.async.wait_group 0;\n")

// ---------------------------------------------------------------------------
// Kernel 1: QKV projection  Y = tf32round(x @ W + b)  (NN GEMM, tf32 mma)
// grid: (DIM/BN, MTOT/BM, 3)
// ---------------------------------------------------------------------------
__global__ __launch_bounds__(NTHREADS, 2)
void qkv_mma_kernel(const float* __restrict__ x,
                    const float* __restrict__ Wq, const float* __restrict__ bq,
                    const float* __restrict__ Wk, const float* __restrict__ bk,
                    const float* __restrict__ Wv, const float* __restrict__ bv)
{
    extern __shared__ float sm[];
    const float *W, *bias;
    float* out;
    if (blockIdx.z == 0)      { W = Wq; bias = bq; out = g_q; }
    else if (blockIdx.z == 1) { W = Wk; bias = bk; out = g_k; }
    else                      { W = Wv; bias = bv; out = g_v; }

    const int row0 = blockIdx.y * BM;
    const int col0 = blockIdx.x * BN;
    const int tid  = threadIdx.x;
    const int lane = tid & 31, warp = tid >> 5;
    const int wm = warp & 3, wn = warp >> 1 >> 1;   // wm 0..3, wn 0..1
    const int gid = lane >> 2, quad = lane & 3;

    const int BUF = AS_ELEMS + BNN_ELEMS;
    const uint32_t sbase = (uint32_t)__cvta_generic_to_shared(sm);

    float acc[2][8][4];
#pragma unroll
    for (int i = 0; i < 2; i++)
#pragma unroll
        for (int j = 0; j < 8; j++)
#pragma unroll
            for (int t = 0; t < 4; t++) acc[i][j][t] = 0.0f;

    const int nIter = DIM / BK;

    // prologue: issue tile 0
    {
        uint32_t sA = sbase;
        uint32_t sB = sA + AS_ELEMS * 4;
#pragma unroll
        for (int i = 0; i < 4; i++) {
            int c = tid + i * 256;
            int m = c >> 3, k4 = c & 7;
            cp16(sA + (m * AS_STRIDE + k4 * 4) * 4,
                 x + (size_t)(row0 + m) * DIM + k4 * 4);
        }
#pragma unroll
        for (int i = 0; i < 4; i++) {
            int c = tid + i * 256;
            int k = c >> 5, n4 = c & 31;
            cp16(sB + (k * BNN_STRIDE + n4 * 4) * 4,
                 W + (size_t)k * DIM + col0 + n4 * 4);
        }
        CP_COMMIT();
    }

    for (int it = 0; it < nIter; ++it) {
        if (it + 1 < nIter) {
            int k0 = (it + 1) * BK;
            uint32_t sA = sbase + ((it + 1) & 1) * BUF * 4;
            uint32_t sB = sA + AS_ELEMS * 4;
#pragma unroll
            for (int i = 0; i < 4; i++) {
                int c = tid + i * 256;
                int m = c >> 3, k4 = c & 7;
                cp16(sA + (m * AS_STRIDE + k4 * 4) * 4,
                     x + (size_t)(row0 + m) * DIM + k0 + k4 * 4);
            }
#pragma unroll
            for (int i = 0; i < 4; i++) {
                int c = tid + i * 256;
                int k = c >> 5, n4 = c & 31;
                cp16(sB + (k * BNN_STRIDE + n4 * 4) * 4,
                     W + (size_t)(k0 + k) * DIM + col0 + n4 * 4);
            }
            CP_COMMIT();
            CP_WAIT1();
        } else {
            CP_WAIT0();
        }
        __syncthreads();

        const float* As = sm + (it & 1) * BUF;
        const float* Bs = As + AS_ELEMS;
#pragma unroll
        for (int kk = 0; kk < BK; kk += 8) {
            uint32_t a[2][4];
#pragma unroll
            for (int mt = 0; mt < 2; mt++) {
                int r = wm * 32 + mt * 16 + gid;
                a[mt][0] = f2tf(As[r * AS_STRIDE + kk + quad]);
                a[mt][1] = f2tf(As[(r + 8) * AS_STRIDE + kk + quad]);
                a[mt][2] = f2tf(As[r * AS_STRIDE + kk + quad + 4]);
                a[mt][3] = f2tf(As[(r + 8) * AS_STRIDE + kk + quad + 4]);
            }
            uint32_t b[8][2];
#pragma unroll
            for (int nt = 0; nt < 8; nt++) {
                int col = wn * 64 + nt * 8 + gid;
                b[nt][0] = f2tf(Bs[(kk + quad) * BNN_STRIDE + col]);
                b[nt][1] = f2tf(Bs[(kk + quad + 4) * BNN_STRIDE + col]);
            }
#pragma unroll
            for (int mt = 0; mt < 2; mt++)
#pragma unroll
                for (int nt = 0; nt < 8; nt++)
                    mma8(acc[mt][nt], a[mt], b[nt]);
        }
        __syncthreads();
    }

    // epilogue: add bias, round to tf32 (so downstream GEMMs skip cvt)
#pragma unroll
    for (int mt = 0; mt < 2; mt++) {
#pragma unroll
        for (int nt = 0; nt < 8; nt++) {
            int col = col0 + wn * 64 + nt * 8 + quad * 2;
            float2 bb = *(const float2*)(bias + col);
            int r = row0 + wm * 32 + mt * 16 + gid;
            float2 o0, o1;
            o0.x = __uint_as_float(f2tf(acc[mt][nt][0] + bb.x));
            o0.y = __uint_as_float(f2tf(acc[mt][nt][1] + bb.y));
            o1.x = __uint_as_float(f2tf(acc[mt][nt][2] + bb.x));
            o1.y = __uint_as_float(f2tf(acc[mt][nt][3] + bb.y));
            *(float2*)(out + (size_t)r * DIM + col)       = o0;
            *(float2*)(out + (size_t)(r + 8) * DIM + col) = o1;
        }
    }
}

// ---------------------------------------------------------------------------
// Kernel 2: causal scores  s[b][i][j] = q[b][i] . k[b][j]  (NT GEMM, tf32 mma)
// q/k already tf32-rounded -> no cvt in the hot loop.
// grid: (SEQ/BN, SEQ/BM, BATCH); blocks above diagonal exit.
// ---------------------------------------------------------------------------
__global__ __launch_bounds__(NTHREADS, 2)
void scores_mma_kernel()
{
    const int row0 = blockIdx.y * BM;
    const int col0 = blockIdx.x * BN;
    if (col0 > row0) return;

    extern __shared__ float sm[];
    const int b = blockIdx.z;
    const float* qb = g_q + (size_t)b * SEQ * DIM;
    const float* kb = g_k + (size_t)b * SEQ * DIM;
    float* sb = g_s + (size_t)b * SEQ * SEQ;

    const int tid  = threadIdx.x;
    const int lane = tid & 31, warp = tid >> 5;
    const int wm = warp & 3, wn = warp >> 2;
    const int gid = lane >> 2, quad = lane & 3;

    const int BUF = AS_ELEMS + BNT_ELEMS;
    const uint32_t sbase = (uint32_t)__cvta_generic_to_shared(sm);

    float acc[2][8][4];
#pragma unroll
    for (int i = 0; i < 2; i++)
#pragma unroll
        for (int j = 0; j < 8; j++)
#pragma unroll
            for (int t = 0; t < 4; t++) acc[i][j][t] = 0.0f;

    const int nIter = DIM / BK;

    {
        uint32_t sA = sbase;
        uint32_t sB = sA + AS_ELEMS * 4;
#pragma unroll
        for (int i = 0; i < 4; i++) {
            int c = tid + i * 256;
            int m = c >> 3, k4 = c & 7;
            cp16(sA + (m * AS_STRIDE + k4 * 4) * 4,
                 qb + (size_t)(row0 + m) * DIM + k4 * 4);
        }
#pragma unroll
        for (int i = 0; i < 4; i++) {
            int c = tid + i * 256;
            int n = c >> 3, k4 = c & 7;
            cp16(sB + (n * BNT_STRIDE + k4 * 4) * 4,
                 kb + (size_t)(col0 + n) * DIM + k4 * 4);
        }
        CP_COMMIT();
    }

    for (int it = 0; it < nIter; ++it) {
        if (it + 1 < nIter) {
            int k0 = (it + 1) * BK;
            uint32_t sA = sbase + ((it + 1) & 1) * BUF * 4;
            uint32_t sB = sA + AS_ELEMS * 4;
#pragma unroll
            for (int i = 0; i < 4; i++) {
                int c = tid + i * 256;
                int m = c >> 3, k4 = c & 7;
                cp16(sA + (m * AS_STRIDE + k4 * 4) * 4,
                     qb + (size_t)(row0 + m) * DIM + k0 + k4 * 4);
            }
#pragma unroll
            for (int i = 0; i < 4; i++) {
                int c = tid + i * 256;
                int n = c >> 3, k4 = c & 7;
                cp16(sB + (n * BNT_STRIDE + k4 * 4) * 4,
                     kb + (size_t)(col0 + n) * DIM + k0 + k4 * 4);
            }
            CP_COMMIT();
            CP_WAIT1();
        } else {
            CP_WAIT0();
        }
        __syncthreads();

        const float* As = sm + (it & 1) * BUF;
        const float* Bs = As + AS_ELEMS;
#pragma unroll
        for (int kk = 0; kk < BK; kk += 8) {
            uint32_t a[2][4];
#pragma unroll
            for (int mt = 0; mt < 2; mt++) {
                int r = wm * 32 + mt * 16 + gid;
                a[mt][0] = __float_as_uint(As[r * AS_STRIDE + kk + quad]);
                a[mt][1] = __float_as_uint(As[(r + 8) * AS_STRIDE + kk + quad]);
                a[mt][2] = __float_as_uint(As[r * AS_STRIDE + kk + quad + 4]);
                a[mt][3] = __float_as_uint(As[(r + 8) * AS_STRIDE + kk + quad + 4]);
            }
            uint32_t b2[8][2];
#pragma unroll
            for (int nt = 0; nt < 8; nt++) {
                int n = wn * 64 + nt * 8 + gid;
                b2[nt][0] = __float_as_uint(Bs[n * BNT_STRIDE + kk + quad]);
                b2[nt][1] = __float_as_uint(Bs[n * BNT_STRIDE + kk + quad + 4]);
            }
#pragma unroll
            for (int mt = 0; mt < 2; mt++)
#pragma unroll
                for (int nt = 0; nt < 8; nt++)
                    mma8(acc[mt][nt], a[mt], b2[nt]);
        }
        __syncthreads();
    }

#pragma unroll
    for (int mt = 0; mt < 2; mt++) {
#pragma unroll
        for (int nt = 0; nt < 8; nt++) {
            int col = col0 + wn * 64 + nt * 8 + quad * 2;
            int r = row0 + wm * 32 + mt * 16 + gid;
            *(float2*)(sb + (size_t)r * SEQ + col)       = *(float2*)&acc[mt][nt][0];
            *(float2*)(sb + (size_t)(r + 8) * SEQ + col) = *(float2*)&acc[mt][nt][2];
        }
    }
}

// ---------------------------------------------------------------------------
// Kernel 3: causal row softmax in-place on g_s; output rounded to tf32.
// Zero-fills (i, roundup128(i+1)) so PV reads full 128-row K tiles.
// grid: (SEQ, BATCH)
// ---------------------------------------------------------------------------
__global__ __launch_bounds__(NTHREADS)
void softmax_kernel()
{
    const int j = blockIdx.x;
    const int b = blockIdx.y;
    float* row = g_s + ((size_t)b * SEQ + j) * SEQ;
    const int n = j + 1;

    __shared__ float red[NTHREADS];
    const int tid = threadIdx.x;
    const float scale = 0.03125f;   // 1/sqrt(1024)

    float m = -INFINITY;
    for (int k = tid; k < n; k += NTHREADS) m = fmaxf(m, row[k]);
    red[tid] = m;
    __syncthreads();
    for (int s = NTHREADS / 2; s > 0; s >>= 1) {
        if (tid < s) red[tid] = fmaxf(red[tid], red[tid + s]);
        __syncthreads();
    }
    m = red[0];
    __syncthreads();

    float sum = 0.0f;
    for (int k = tid; k < n; k += NTHREADS) {
        float e = __expf((row[k] - m) * scale);
        row[k] = e;
        sum += e;
    }
    red[tid] = sum;
    __syncthreads();
    for (int s = NTHREADS / 2; s > 0; s >>= 1) {
        if (tid < s) red[tid] += red[tid + s];
        __syncthreads();
    }
    const float rsum = 1.0f / red[0];
    __syncthreads();

    for (int k = tid; k < n; k += NTHREADS)
        row[k] = __uint_as_float(f2tf(row[k] * rsum));
    const int npad = ((j >> 7) + 1) << 7;
    for (int k = n + tid; k < npad; k += NTHREADS) row[k] = 0.0f;
}

// ---------------------------------------------------------------------------
// Kernel 4: out = w @ v (NN GEMM, tf32 mma), K loop truncated causally.
// w and v already tf32-rounded -> no cvt in the hot loop.
// grid: (DIM/BN, SEQ/BM, BATCH)
// ---------------------------------------------------------------------------
__global__ __launch_bounds__(NTHREADS, 2)
void pv_mma_kernel(float* __restrict__ out_all)
{
    extern __shared__ float sm[];
    const int row0 = blockIdx.y * BM;
    const int col0 = blockIdx.x * BN;
    const int b = blockIdx.z;

    const float* wb = g_s + (size_t)b * SEQ * SEQ;
    const float* vb = g_v + (size_t)b * SEQ * DIM;
    float* out = out_all + (size_t)b * SEQ * DIM;

    const int tid  = threadIdx.x;
    const int lane = tid & 31, warp = tid >> 5;
    const int wm = warp & 3, wn = warp >> 2;
    const int gid = lane >> 2, quad = lane & 3;

    const int BUF = AS_ELEMS + BNN_ELEMS;
    const uint32_t sbase = (uint32_t)__cvta_generic_to_shared(sm);

    float acc[2][8][4];
#pragma unroll
    for (int i = 0; i < 2; i++)
#pragma unroll
        for (int j = 0; j < 8; j++)
#pragma unroll
            for (int t = 0; t < 4; t++) acc[i][j][t] = 0.0f;

    const int nIter = (row0 + BM) / BK;   // causal truncation

    {
        uint32_t sA = sbase;
        uint32_t sB = sA + AS_ELEMS * 4;
#pragma unroll
        for (int i = 0; i < 4; i++) {
            int c = tid + i * 256;
            int m = c >> 3, k4 = c & 7;
            cp16(sA + (m * AS_STRIDE + k4 * 4) * 4,
                 wb + (size_t)(row0 + m) * SEQ + k4 * 4);
        }
#pragma unroll
        for (int i = 0; i < 4; i++) {
            int c = tid + i * 256;
            int k = c >> 5, n4 = c & 31;
            cp16(sB + (k * BNN_STRIDE + n4 * 4) * 4,
                 vb + (size_t)k * DIM + col0 + n4 * 4);
        }
        CP_COMMIT();
    }

    for (int it = 0; it < nIter; ++it) {
        if (it + 1 < nIter) {
            int k0 = (it + 1) * BK;
            uint32_t sA = sbase + ((it + 1) & 1) * BUF * 4;
            uint32_t sB = sA + AS_ELEMS * 4;
#pragma unroll
            for (int i = 0; i < 4; i++) {
                int c = tid + i * 256;
                int m = c >> 3, k4 = c & 7;
                cp16(sA + (m * AS_STRIDE + k4 * 4) * 4,
                     wb + (size_t)(row0 + m) * SEQ + k0 + k4 * 4);
            }
#pragma unroll
            for (int i = 0; i < 4; i++) {
                int c = tid + i * 256;
                int k = c >> 5, n4 = c & 31;
                cp16(sB + (k * BNN_STRIDE + n4 * 4) * 4,
                     vb + (size_t)(k0 + k) * DIM + col0 + n4 * 4);
            }
            CP_COMMIT();
            CP_WAIT1();
        } else {
            CP_WAIT0();
        }
        __syncthreads();

        const float* As = sm + (it & 1) * BUF;
        const float* Bs = As + AS_ELEMS;
#pragma unroll
        for (int kk = 0; kk < BK; kk += 8) {
            uint32_t a[2][4];
#pragma unroll
            for (int mt = 0; mt < 2; mt++) {
                int r = wm * 32 + mt * 16 + gid;
                a[mt][0] = __float_as_uint(As[r * AS_STRIDE + kk + quad]);
                a[mt][1] = __float_as_uint(As[(r + 8) * AS_STRIDE + kk + quad]);
                a[mt][2] = __float_as_uint(As[r * AS_STRIDE + kk + quad + 4]);
                a[mt][3] = __float_as_uint(As[(r + 8) * AS_STRIDE + kk + quad + 4]);
            }
            uint32_t b2[8][2];
#pragma unroll
            for (int nt = 0; nt < 8; nt++) {
                int col = wn * 64 + nt * 8 + gid;
                b2[nt][0] = __float_as_uint(Bs[(kk + quad) * BNN_STRIDE + col]);
                b2[nt][1] = __float_as_uint(Bs[(kk + quad + 4) * BNN_STRIDE + col]);
            }
#pragma unroll
            for (int mt = 0; mt < 2; mt++)
#pragma unroll
                for (int nt = 0; nt < 8; nt++)
                    mma8(acc[mt][nt], a[mt], b2[nt]);
        }
        __syncthreads();
    }

#pragma unroll
    for (int mt = 0; mt < 2; mt++) {
#pragma unroll
        for (int nt = 0; nt < 8; nt++) {
            int col = col0 + wn * 64 + nt * 8 + quad * 2;
            int r = row0 + wm * 32 + mt * 16 + gid;
            *(float2*)(out + (size_t)r * DIM + col)       = *(float2*)&acc[mt][nt][0];
            *(float2*)(out + (size_t)(r + 8) * DIM + col) = *(float2*)&acc[mt][nt][2];
        }
    }
}

// ---------------------------------------------------------------------------
extern "C" void kernel_launch(void* const* d_in, const int* in_sizes, int n_in,
                              void* d_out, int out_size)
{
    const float* x  = (const float*)d_in[0];
    const float* Wq = (const float*)d_in[1];
    const float* bq = (const float*)d_in[2];
    const float* Wk = (const float*)d_in[3];
    const float* bk = (const float*)d_in[4];
    const float* Wv = (const float*)d_in[5];
    const float* bv = (const float*)d_in[6];
    float* out = (float*)d_out;

    // Opt-in to >48KB dynamic smem (idempotent; host-side, not captured)
    cudaFuncSetAttribute(qkv_mma_kernel,    cudaFuncAttributeMaxDynamicSharedMemorySize, SMEM_NN_BYTES);
    cudaFuncSetAttribute(scores_mma_kernel, cudaFuncAttributeMaxDynamicSharedMemorySize, SMEM_NT_BYTES);
    cudaFuncSetAttribute(pv_mma_kernel,     cudaFuncAttributeMaxDynamicSharedMemorySize, SMEM_NN_BYTES);

    {
        dim3 grid(DIM / BN, MTOT / BM, 3);
        qkv_mma_kernel<<<grid, NTHREADS, SMEM_NN_BYTES>>>(x, Wq, bq, Wk, bk, Wv, bv);
    }
    {
        dim3 grid(SEQ / BN, SEQ / BM, BATCH);
        scores_mma_kernel<<<grid, NTHREADS, SMEM_NT_BYTES>>>();
    }
    {
        dim3 grid(SEQ, BATCH);
        softmax_kernel<<<grid, NTHREADS>>>();
    }
    {
        dim3 grid(DIM / BN, SEQ / BM, BATCH);
        pv_mma_kernel<<<grid, NTHREADS, SMEM_NN_BYTES>>>(out);
    }
}

// round 4
// speedup vs baseline: 4.4127x; 1.2762x over previous
#include <cuda_runtime.h>
#include <math.h>
#include <stdint.h>

// ---------------------------------------------------------------------------
// Problem constants
// ---------------------------------------------------------------------------
#define BATCH 4
#define SEQ   4096
#define DIM   1024
#define MTOT  (BATCH * SEQ)     // 16384

#define NTHR_G 128              // 4 warps per GEMM CTA
#define NTHR_S 256
#define STAGES 3
#define TILE_B  16384           // 128 rows x 128 bytes (BK=32 floats)
#define STAGE_B (2 * TILE_B)
#define SMEM_BYTES (STAGES * STAGE_B)   // 98304

// ---------------------------------------------------------------------------
// Scratch (__device__ globals: allocation-free rule)
// ---------------------------------------------------------------------------
__device__ float g_q[MTOT * DIM];
__device__ float g_k[MTOT * DIM];
__device__ float g_v[MTOT * DIM];
__device__ float g_s[(size_t)BATCH * SEQ * SEQ];    // 256 MB scores/weights
__device__ float g_xr[MTOT * DIM];                  // tf32-rounded x
__device__ float g_wt[3 * DIM * DIM];               // W^T, rounded (q,k,v)
__device__ float g_vt[(size_t)BATCH * DIM * SEQ];   // v^T per batch

// ---------------------------------------------------------------------------
// Helpers
// ---------------------------------------------------------------------------
__device__ __forceinline__ uint32_t f2tf(float f) {
    uint32_t u;
    asm("cvt.rna.tf32.f32 %0, %1;" : "=r"(u) : "f"(f));
    return u;
}

__device__ __forceinline__ uint32_t smem_u32(const void* p) {
    return (uint32_t)__cvta_generic_to_shared(p);
}

__device__ __forceinline__ void cp16(uint32_t dst, const void* src) {
    asm volatile("cp.async.cg.shared.global [%0], [%1], 16;\n" :: "r"(dst), "l"(src));
}
#define CP_COMMIT() asm volatile("cp.async.commit_group;\n")
#define CP_WAIT1()  asm volatile("cp.async.wait_group 1;\n")
#define CP_WAIT0()  asm volatile("cp.async.wait_group 0;\n")

__device__ __forceinline__ void ldsm4(uint32_t* r, uint32_t addr) {
    asm volatile("ldmatrix.sync.aligned.m8n8.x4.shared.b16 {%0,%1,%2,%3}, [%4];"
                 : "=r"(r[0]), "=r"(r[1]), "=r"(r[2]), "=r"(r[3]) : "r"(addr));
}

__device__ __forceinline__ void mma8(float* d, const uint32_t* a, const uint32_t* b) {
    asm volatile(
        "mma.sync.aligned.m16n8k8.row.col.f32.tf32.tf32.f32 "
        "{%0,%1,%2,%3}, {%4,%5,%6,%7}, {%8,%9}, {%0,%1,%2,%3};\n"
        : "+f"(d[0]), "+f"(d[1]), "+f"(d[2]), "+f"(d[3])
        : "r"(a[0]), "r"(a[1]), "r"(a[2]), "r"(a[3]), "r"(b[0]), "r"(b[1]));
}

// ---------------------------------------------------------------------------
// Tile fill: 128 rows x 32 floats (128B/row), swizzled chunk = c16 ^ (r&7).
// 128 threads, 8 chunks each.
// ---------------------------------------------------------------------------
__device__ __forceinline__ void fill_tile(uint32_t sdst, const float* __restrict__ g,
                                          int ld, int k0) {
    const int tid = threadIdx.x;
#pragma unroll
    for (int i = 0; i < 8; i++) {
        int c = tid + i * 128;
        int r = c >> 3, c16 = c & 7;
        cp16(sdst + r * 128 + ((c16 ^ (r & 7)) << 4),
             g + (size_t)r * ld + k0 + c16 * 4);
    }
}

// ---------------------------------------------------------------------------
// Unified NT GEMM: C[128x128 tile] = A(row-major,K-contig) . B^T(K-contig rows)
// Warp tile 64x64, ldmatrix fragment loads, 3-stage cp.async pipeline.
// MODE 0: QKV    A=g_xr,  B=g_wt[z], C=g_q/g_k/g_v (+bias, tf32-rounded)
// MODE 1: scores A=g_q[z],B=g_k[z],  C=g_s[z]  (causal block skip)
// MODE 2: PV     A=g_s[z],B=g_vt[z], C=out[z]  (K truncated at row0+128)
// ---------------------------------------------------------------------------
template <int MODE>
__global__ __launch_bounds__(NTHR_G, 2)
void gemm_nt(float* __restrict__ Cout,
             const float* __restrict__ b0, const float* __restrict__ b1,
             const float* __restrict__ b2)
{
    const int row0 = blockIdx.y * 128;
    const int col0 = blockIdx.x * 128;
    const int z = blockIdx.z;
    if (MODE == 1 && col0 > row0) return;

    const float *A, *B, *bias = nullptr;
    float* C;
    int lda, ldb, ldc, nK;
    if (MODE == 0) {
        A = g_xr; lda = DIM;
        B = g_wt + (size_t)z * DIM * DIM; ldb = DIM;
        C = (z == 0 ? g_q : (z == 1 ? g_k : g_v)); ldc = DIM;
        bias = (z == 0 ? b0 : (z == 1 ? b1 : b2));
        nK = DIM / 32;
    } else if (MODE == 1) {
        A = g_q + (size_t)z * SEQ * DIM; lda = DIM;
        B = g_k + (size_t)z * SEQ * DIM; ldb = DIM;
        C = g_s + (size_t)z * SEQ * SEQ; ldc = SEQ;
        nK = DIM / 32;
    } else {
        A = g_s + (size_t)z * SEQ * SEQ; lda = SEQ;
        B = g_vt + (size_t)z * DIM * SEQ; ldb = SEQ;
        C = Cout + (size_t)z * SEQ * DIM; ldc = DIM;
        nK = (row0 + 128) / 32;
    }
    const float* Arow = A + (size_t)row0 * lda;
    const float* Brow = B + (size_t)col0 * ldb;

    extern __shared__ char smem[];
    const uint32_t sbase = smem_u32(smem);

    const int tid  = threadIdx.x;
    const int lane = tid & 31, warp = tid >> 5;
    const int wm = warp & 1, wn = warp >> 1;      // 2x2 warp grid of 64x64
    const int mat = lane >> 3, rl = lane & 7;     // ldmatrix address lanes

    float acc[4][8][4];
#pragma unroll
    for (int i = 0; i < 4; i++)
#pragma unroll
        for (int j = 0; j < 8; j++)
#pragma unroll
            for (int t = 0; t < 4; t++) acc[i][j][t] = 0.0f;

    // prologue: stages 0 and 1
    fill_tile(sbase, Arow, lda, 0);
    fill_tile(sbase + TILE_B, Brow, ldb, 0);
    CP_COMMIT();
    fill_tile(sbase + STAGE_B, Arow, lda, 32);
    fill_tile(sbase + STAGE_B + TILE_B, Brow, ldb, 32);
    CP_COMMIT();

    for (int it = 0; it < nK; ++it) {
        if (it + 1 < nK) { CP_WAIT1(); } else { CP_WAIT0(); }
        __syncthreads();

        // prefetch stage it+2 (slot was consumed at iteration it-1)
        if (it + 2 < nK) {
            const int slot = (it + 2) % STAGES;
            fill_tile(sbase + slot * STAGE_B, Arow, lda, (it + 2) * 32);
            fill_tile(sbase + slot * STAGE_B + TILE_B, Brow, ldb, (it + 2) * 32);
            CP_COMMIT();
        }

        const uint32_t sA = sbase + (it % STAGES) * STAGE_B;
        const uint32_t sB = sA + TILE_B;

#pragma unroll
        for (int kk8 = 0; kk8 < 4; kk8++) {
            const int klo = kk8 * 2;   // low 16B-chunk index of this k8 step

            // A fragments: 4 m-tiles, each one ldmatrix.x4
            uint32_t a[4][4];
#pragma unroll
            for (int mt = 0; mt < 4; mt++) {
                int row = wm * 64 + mt * 16 + ((mat & 1) << 3) + rl;
                int c16 = klo + (mat >> 1);
                ldsm4(a[mt], sA + row * 128 + ((c16 ^ (row & 7)) << 4));
            }
            // B fragments: 8 n-tiles, two per ldmatrix.x4
            uint32_t b[8][2];
#pragma unroll
            for (int t = 0; t < 4; t++) {
                int nrow = wn * 64 + (2 * t + (mat >> 1)) * 8 + rl;
                int c16 = klo + (mat & 1);
                uint32_t r4[4];
                ldsm4(r4, sB + nrow * 128 + ((c16 ^ (nrow & 7)) << 4));
                b[2 * t][0] = r4[0]; b[2 * t][1] = r4[1];
                b[2 * t + 1][0] = r4[2]; b[2 * t + 1][1] = r4[3];
            }
#pragma unroll
            for (int mt = 0; mt < 4; mt++)
#pragma unroll
                for (int nt = 0; nt < 8; nt++)
                    mma8(acc[mt][nt], a[mt], b[nt]);
        }
        __syncthreads();
    }

    // Epilogue
    const int gr0 = row0 + wm * 64 + (lane >> 2);
    const int gc0 = col0 + wn * 64 + (lane & 3) * 2;
#pragma unroll
    for (int mt = 0; mt < 4; mt++) {
#pragma unroll
        for (int nt = 0; nt < 8; nt++) {
            const int gr = gr0 + mt * 16;
            const int gc = gc0 + nt * 8;
            if (MODE == 0) {
                float2 bb = *(const float2*)(bias + gc);
                float2 o0, o1;
                o0.x = __uint_as_float(f2tf(acc[mt][nt][0] + bb.x));
                o0.y = __uint_as_float(f2tf(acc[mt][nt][1] + bb.y));
                o1.x = __uint_as_float(f2tf(acc[mt][nt][2] + bb.x));
                o1.y = __uint_as_float(f2tf(acc[mt][nt][3] + bb.y));
                *(float2*)(C + (size_t)gr * ldc + gc)       = o0;
                *(float2*)(C + (size_t)(gr + 8) * ldc + gc) = o1;
            } else {
                *(float2*)(C + (size_t)gr * ldc + gc)       = *(float2*)&acc[mt][nt][0];
                *(float2*)(C + (size_t)(gr + 8) * ldc + gc) = *(float2*)&acc[mt][nt][2];
            }
        }
    }
}

// ---------------------------------------------------------------------------
// Prep kernels
// ---------------------------------------------------------------------------
__global__ __launch_bounds__(256)
void round_x_kernel(const float* __restrict__ x)
{
    const int idx = blockIdx.x * 256 + threadIdx.x;
    float4 v = *(const float4*)(x + (size_t)idx * 4);
    v.x = __uint_as_float(f2tf(v.x));
    v.y = __uint_as_float(f2tf(v.y));
    v.z = __uint_as_float(f2tf(v.z));
    v.w = __uint_as_float(f2tf(v.w));
    *(float4*)(g_xr + (size_t)idx * 4) = v;
}

__global__ __launch_bounds__(256)
void transpose_w_kernel(const float* __restrict__ Wq, const float* __restrict__ Wk,
                        const float* __restrict__ Wv)
{
    __shared__ float t[32][33];
    const int zz = blockIdx.z;
    const float* W = (zz == 0 ? Wq : (zz == 1 ? Wk : Wv));
    const int x0 = blockIdx.x * 32;   // n
    const int y0 = blockIdx.y * 32;   // k
    const int tx = threadIdx.x & 31, ty = threadIdx.x >> 5;
#pragma unroll
    for (int j = 0; j < 4; j++)
        t[ty + j * 8][tx] = W[(size_t)(y0 + ty + j * 8) * DIM + x0 + tx];
    __syncthreads();
    float* out = g_wt + (size_t)zz * DIM * DIM;
#pragma unroll
    for (int j = 0; j < 4; j++)
        out[(size_t)(x0 + ty + j * 8) * DIM + y0 + tx] =
            __uint_as_float(f2tf(t[tx][ty + j * 8]));
}

__global__ __launch_bounds__(256)
void transpose_v_kernel()
{
    __shared__ float t[32][33];
    const int b = blockIdx.z;
    const float* vsrc = g_v + (size_t)b * SEQ * DIM;
    float* vdst = g_vt + (size_t)b * DIM * SEQ;
    const int x0 = blockIdx.x * 32;   // d
    const int y0 = blockIdx.y * 32;   // s
    const int tx = threadIdx.x & 31, ty = threadIdx.x >> 5;
#pragma unroll
    for (int j = 0; j < 4; j++)
        t[ty + j * 8][tx] = vsrc[(size_t)(y0 + ty + j * 8) * DIM + x0 + tx];
    __syncthreads();
#pragma unroll
    for (int j = 0; j < 4; j++)
        vdst[(size_t)(x0 + ty + j * 8) * SEQ + y0 + tx] = t[tx][ty + j * 8];
}

// ---------------------------------------------------------------------------
// Causal softmax (in-place, tf32-rounded output, zero-pad to 128 boundary)
// ---------------------------------------------------------------------------
__global__ __launch_bounds__(NTHR_S)
void softmax_kernel()
{
    const int j = blockIdx.x;
    const int b = blockIdx.y;
    float* row = g_s + ((size_t)b * SEQ + j) * SEQ;
    const int n = j + 1;
    const int n4 = n & ~3;

    __shared__ float red[NTHR_S];
    const int tid = threadIdx.x;
    const float scale = 0.03125f;   // 1/sqrt(1024)

    float m = -INFINITY;
    for (int k = 4 * tid; k < n4; k += 4 * NTHR_S) {
        float4 v = *(const float4*)(row + k);
        m = fmaxf(m, fmaxf(fmaxf(v.x, v.y), fmaxf(v.z, v.w)));
    }
    for (int k = n4 + tid; k < n; k += NTHR_S) m = fmaxf(m, row[k]);
    red[tid] = m;
    __syncthreads();
    for (int s = NTHR_S / 2; s > 0; s >>= 1) {
        if (tid < s) red[tid] = fmaxf(red[tid], red[tid + s]);
        __syncthreads();
    }
    m = red[0];
    __syncthreads();

    float sum = 0.0f;
    for (int k = 4 * tid; k < n4; k += 4 * NTHR_S) {
        float4 v = *(const float4*)(row + k);
        v.x = __expf((v.x - m) * scale);
        v.y = __expf((v.y - m) * scale);
        v.z = __expf((v.z - m) * scale);
        v.w = __expf((v.w - m) * scale);
        sum += v.x + v.y + v.z + v.w;
        *(float4*)(row + k) = v;
    }
    for (int k = n4 + tid; k < n; k += NTHR_S) {
        float e = __expf((row[k] - m) * scale);
        row[k] = e;
        sum += e;
    }
    red[tid] = sum;
    __syncthreads();
    for (int s = NTHR_S / 2; s > 0; s >>= 1) {
        if (tid < s) red[tid] += red[tid + s];
        __syncthreads();
    }
    const float rsum = 1.0f / red[0];
    __syncthreads();

    for (int k = 4 * tid; k < n4; k += 4 * NTHR_S) {
        float4 v = *(const float4*)(row + k);
        v.x = __uint_as_float(f2tf(v.x * rsum));
        v.y = __uint_as_float(f2tf(v.y * rsum));
        v.z = __uint_as_float(f2tf(v.z * rsum));
        v.w = __uint_as_float(f2tf(v.w * rsum));
        *(float4*)(row + k) = v;
    }
    for (int k = n4 + tid; k < n; k += NTHR_S)
        row[k] = __uint_as_float(f2tf(row[k] * rsum));

    const int npad = ((j >> 7) + 1) << 7;
    for (int k = n + tid; k < npad; k += NTHR_S) row[k] = 0.0f;
}

// ---------------------------------------------------------------------------
extern "C" void kernel_launch(void* const* d_in, const int* in_sizes, int n_in,
                              void* d_out, int out_size)
{
    const float* x  = (const float*)d_in[0];
    const float* Wq = (const float*)d_in[1];
    const float* bq = (const float*)d_in[2];
    const float* Wk = (const float*)d_in[3];
    const float* bk = (const float*)d_in[4];
    const float* Wv = (const float*)d_in[5];
    const float* bv = (const float*)d_in[6];
    float* out = (float*)d_out;

    cudaFuncSetAttribute(gemm_nt<0>, cudaFuncAttributeMaxDynamicSharedMemorySize, SMEM_BYTES);
    cudaFuncSetAttribute(gemm_nt<1>, cudaFuncAttributeMaxDynamicSharedMemorySize, SMEM_BYTES);
    cudaFuncSetAttribute(gemm_nt<2>, cudaFuncAttributeMaxDynamicSharedMemorySize, SMEM_BYTES);

    // prep
    round_x_kernel<<<MTOT * DIM / (256 * 4), 256>>>(x);
    {
        dim3 g(DIM / 32, DIM / 32, 3);
        transpose_w_kernel<<<g, 256>>>(Wq, Wk, Wv);
    }
    // QKV
    {
        dim3 g(DIM / 128, MTOT / 128, 3);
        gemm_nt<0><<<g, NTHR_G, SMEM_BYTES>>>(nullptr, bq, bk, bv);
    }
    // v^T, scores
    {
        dim3 g(DIM / 32, SEQ / 32, BATCH);
        transpose_v_kernel<<<g, 256>>>();
    }
    {
        dim3 g(SEQ / 128, SEQ / 128, BATCH);
        gemm_nt<1><<<g, NTHR_G, SMEM_BYTES>>>(nullptr, nullptr, nullptr, nullptr);
    }
    // softmax
    {
        dim3 g(SEQ, BATCH);
        softmax_kernel<<<g, NTHR_S>>>();
    }
    // PV
    {
        dim3 g(DIM / 128, SEQ / 128, BATCH);
        gemm_nt<2><<<g, NTHR_G, SMEM_BYTES>>>(out, nullptr, nullptr, nullptr);
    }
}

// round 6
// speedup vs baseline: 5.3080x; 1.2029x over previous
#include <cuda_runtime.h>
#include <cuda_fp16.h>
#include <math.h>
#include <stdint.h>

// ---------------------------------------------------------------------------
// Problem constants
// ---------------------------------------------------------------------------
#define BATCH 4
#define SEQ   4096
#define DIM   1024
#define MTOT  (BATCH * SEQ)     // 16384

#define NTHR_G 128              // 4 warps per GEMM CTA
#define NTHR_S 256
#define STAGES 3
#define BK     64               // halves per k-chunk (128 B per row)
#define TILE_B  16384           // 128 rows x 128 bytes
#define STAGE_B (2 * TILE_B)
#define SMEM_BYTES (STAGES * STAGE_B)   // 98304

#define NEG_BIG (-3.0e38f)      // finite -inf substitute (avoids inf-inf=nan in merges)

// ---------------------------------------------------------------------------
// Scratch (__device__ globals: allocation-free rule)
// ---------------------------------------------------------------------------
__device__ __half g_xh[MTOT * DIM];                  // fp16 x
__device__ __half g_wth[3 * DIM * DIM];              // W^T fp16 (q,k,v)
__device__ __half g_qh[MTOT * DIM];
__device__ __half g_kh[MTOT * DIM];
__device__ __half g_vh[MTOT * DIM];
__device__ __half g_vth[(size_t)BATCH * DIM * SEQ];  // v^T fp16
__device__ float  g_s[(size_t)BATCH * SEQ * SEQ];    // raw scores fp32
__device__ __half g_sh[(size_t)BATCH * SEQ * SEQ];   // softmax weights fp16

// ---------------------------------------------------------------------------
// Helpers
// ---------------------------------------------------------------------------
__device__ __forceinline__ uint32_t smem_u32(const void* p) {
    return (uint32_t)__cvta_generic_to_shared(p);
}

__device__ __forceinline__ void cp16(uint32_t dst, const void* src) {
    asm volatile("cp.async.cg.shared.global [%0], [%1], 16;\n" :: "r"(dst), "l"(src));
}
#define CP_COMMIT() asm volatile("cp.async.commit_group;\n")
#define CP_WAIT1()  asm volatile("cp.async.wait_group 1;\n")
#define CP_WAIT0()  asm volatile("cp.async.wait_group 0;\n")

__device__ __forceinline__ void ldsm4(uint32_t* r, uint32_t addr) {
    asm volatile("ldmatrix.sync.aligned.m8n8.x4.shared.b16 {%0,%1,%2,%3}, [%4];"
                 : "=r"(r[0]), "=r"(r[1]), "=r"(r[2]), "=r"(r[3]) : "r"(addr));
}

__device__ __forceinline__ void mma16(float* d, const uint32_t* a, const uint32_t* b) {
    asm volatile(
        "mma.sync.aligned.m16n8k16.row.col.f32.f16.f16.f32 "
        "{%0,%1,%2,%3}, {%4,%5,%6,%7}, {%8,%9}, {%0,%1,%2,%3};\n"
        : "+f"(d[0]), "+f"(d[1]), "+f"(d[2]), "+f"(d[3])
        : "r"(a[0]), "r"(a[1]), "r"(a[2]), "r"(a[3]), "r"(b[0]), "r"(b[1]));
}

// ---------------------------------------------------------------------------
// Tile fill: 128 rows x 64 halves (128B/row), swizzled chunk = c16 ^ (r&7).
// 128 threads, 8 chunks each.
// ---------------------------------------------------------------------------
__device__ __forceinline__ void fill_tile(uint32_t sdst, const __half* __restrict__ g,
                                          int ld, int k0) {
    const int tid = threadIdx.x;
#pragma unroll
    for (int i = 0; i < 8; i++) {
        int c = tid + i * 128;
        int r = c >> 3, c16 = c & 7;
        cp16(sdst + r * 128 + ((c16 ^ (r & 7)) << 4),
             g + (size_t)r * ld + k0 + c16 * 8);
    }
}

// ---------------------------------------------------------------------------
// Unified NT fp16 GEMM: C[128x128] = A(row-major,K-contig) . B^T(K-contig rows)
// Warp tile 64x64, m16n8k16, 3-stage cp.async pipeline.
// MODE 0: QKV    A=g_xh,  B=g_wth[z], C=g_qh/g_kh/g_vh (+bias fp32, ->fp16)
// MODE 1: scores A=g_qh[z],B=g_kh[z], C=g_s (fp32), causal block skip
// MODE 2: PV     A=g_sh[z],B=g_vth[z],C=out (fp32),  K truncated at row0+128
// ---------------------------------------------------------------------------
template <int MODE>
__global__ __launch_bounds__(NTHR_G, 2)
void gemm_nt(float* __restrict__ Cout,
             const float* __restrict__ b0, const float* __restrict__ b1,
             const float* __restrict__ b2)
{
    const int row0 = blockIdx.y * 128;
    const int col0 = blockIdx.x * 128;
    const int z = blockIdx.z;
    if (MODE == 1 && col0 > row0) return;

    const __half *A, *B;
    const float* bias = nullptr;
    __half* Ch = nullptr;
    float* Cf = nullptr;
    int lda, ldb, ldc, nK;
    if (MODE == 0) {
        A = g_xh; lda = DIM;
        B = g_wth + (size_t)z * DIM * DIM; ldb = DIM;
        Ch = (z == 0 ? g_qh : (z == 1 ? g_kh : g_vh)); ldc = DIM;
        bias = (z == 0 ? b0 : (z == 1 ? b1 : b2));
        nK = DIM / BK;
    } else if (MODE == 1) {
        A = g_qh + (size_t)z * SEQ * DIM; lda = DIM;
        B = g_kh + (size_t)z * SEQ * DIM; ldb = DIM;
        Cf = g_s + (size_t)z * SEQ * SEQ; ldc = SEQ;
        nK = DIM / BK;
    } else {
        A = g_sh + (size_t)z * SEQ * SEQ; lda = SEQ;
        B = g_vth + (size_t)z * DIM * SEQ; ldb = SEQ;
        Cf = Cout + (size_t)z * SEQ * DIM; ldc = DIM;
        nK = (row0 + 128) / BK;
    }
    const __half* Arow = A + (size_t)row0 * lda;
    const __half* Brow = B + (size_t)col0 * ldb;

    extern __shared__ char smem[];
    const uint32_t sbase = smem_u32(smem);

    const int tid  = threadIdx.x;
    const int lane = tid & 31, warp = tid >> 5;
    const int wm = warp & 1, wn = warp >> 1;      // 2x2 warp grid of 64x64
    const int mat = lane >> 3, rl = lane & 7;     // ldmatrix address lanes

    float acc[4][8][4];
#pragma unroll
    for (int i = 0; i < 4; i++)
#pragma unroll
        for (int j = 0; j < 8; j++)
#pragma unroll
            for (int t = 0; t < 4; t++) acc[i][j][t] = 0.0f;

    // prologue: stages 0 and 1
    fill_tile(sbase, Arow, lda, 0);
    fill_tile(sbase + TILE_B, Brow, ldb, 0);
    CP_COMMIT();
    fill_tile(sbase + STAGE_B, Arow, lda, BK);
    fill_tile(sbase + STAGE_B + TILE_B, Brow, ldb, BK);
    CP_COMMIT();

    for (int it = 0; it < nK; ++it) {
        if (it + 1 < nK) { CP_WAIT1(); } else { CP_WAIT0(); }
        __syncthreads();

        if (it + 2 < nK) {
            const int slot = (it + 2) % STAGES;
            fill_tile(sbase + slot * STAGE_B, Arow, lda, (it + 2) * BK);
            fill_tile(sbase + slot * STAGE_B + TILE_B, Brow, ldb, (it + 2) * BK);
            CP_COMMIT();
        }

        const uint32_t sA = sbase + (it % STAGES) * STAGE_B;
        const uint32_t sB = sA + TILE_B;

#pragma unroll
        for (int kk = 0; kk < 4; kk++) {          // 4 x k16 per BK=64
            const int klo = kk * 2;               // 16B chunk index

            // A fragments: mat g covers (m8 block = g&1, k8 block = g>>1)
            uint32_t a[4][4];
#pragma unroll
            for (int mt = 0; mt < 4; mt++) {
                int row = wm * 64 + mt * 16 + ((mat & 1) << 3) + rl;
                int c16 = klo + (mat >> 1);
                ldsm4(a[mt], sA + row * 128 + ((c16 ^ (row & 7)) << 4));
            }
            // B fragments: mat g covers (n8 block = g>>1, k8 block = g&1)
            uint32_t b[8][2];
#pragma unroll
            for (int t = 0; t < 4; t++) {
                int nrow = wn * 64 + t * 16 + ((mat >> 1) << 3) + rl;
                int c16 = klo + (mat & 1);
                uint32_t r4[4];
                ldsm4(r4, sB + nrow * 128 + ((c16 ^ (nrow & 7)) << 4));
                b[2 * t][0] = r4[0]; b[2 * t][1] = r4[1];
                b[2 * t + 1][0] = r4[2]; b[2 * t + 1][1] = r4[3];
            }
#pragma unroll
            for (int mt = 0; mt < 4; mt++)
#pragma unroll
                for (int nt = 0; nt < 8; nt++)
                    mma16(acc[mt][nt], a[mt], b[nt]);
        }
        __syncthreads();
    }

    // Epilogue
    const int gr0 = row0 + wm * 64 + (lane >> 2);
    const int gc0 = col0 + wn * 64 + (lane & 3) * 2;
#pragma unroll
    for (int mt = 0; mt < 4; mt++) {
#pragma unroll
        for (int nt = 0; nt < 8; nt++) {
            const int gr = gr0 + mt * 16;
            const int gc = gc0 + nt * 8;
            if (MODE == 0) {
                float2 bb = *(const float2*)(bias + gc);
                __half2 h0 = __floats2half2_rn(acc[mt][nt][0] + bb.x,
                                               acc[mt][nt][1] + bb.y);
                __half2 h1 = __floats2half2_rn(acc[mt][nt][2] + bb.x,
                                               acc[mt][nt][3] + bb.y);
                *(__half2*)(Ch + (size_t)gr * ldc + gc)       = h0;
                *(__half2*)(Ch + (size_t)(gr + 8) * ldc + gc) = h1;
            } else {
                *(float2*)(Cf + (size_t)gr * ldc + gc)       = *(float2*)&acc[mt][nt][0];
                *(float2*)(Cf + (size_t)(gr + 8) * ldc + gc) = *(float2*)&acc[mt][nt][2];
            }
        }
    }
}

// ---------------------------------------------------------------------------
// Prep kernels
// ---------------------------------------------------------------------------
__global__ __launch_bounds__(256)
void conv_x_kernel(const float* __restrict__ x)
{
    const int idx = blockIdx.x * 256 + threadIdx.x;   // one float4 each
    float4 v = *(const float4*)(x + (size_t)idx * 4);
    __half2* dst = (__half2*)(g_xh + (size_t)idx * 4);
    dst[0] = __floats2half2_rn(v.x, v.y);
    dst[1] = __floats2half2_rn(v.z, v.w);
}

__global__ __launch_bounds__(256)
void transpose_w_kernel(const float* __restrict__ Wq, const float* __restrict__ Wk,
                        const float* __restrict__ Wv)
{
    __shared__ float t[32][33];
    const int zz = blockIdx.z;
    const float* W = (zz == 0 ? Wq : (zz == 1 ? Wk : Wv));
    const int x0 = blockIdx.x * 32;   // n
    const int y0 = blockIdx.y * 32;   // k
    const int tx = threadIdx.x & 31, ty = threadIdx.x >> 5;
#pragma unroll
    for (int j = 0; j < 4; j++)
        t[ty + j * 8][tx] = W[(size_t)(y0 + ty + j * 8) * DIM + x0 + tx];
    __syncthreads();
    __half* out = g_wth + (size_t)zz * DIM * DIM;
#pragma unroll
    for (int j = 0; j < 4; j++)
        out[(size_t)(x0 + ty + j * 8) * DIM + y0 + tx] = __float2half_rn(t[tx][ty + j * 8]);
}

__global__ __launch_bounds__(256)
void transpose_v_kernel()
{
    __shared__ __half t[32][34];
    const int b = blockIdx.z;
    const __half* vsrc = g_vh + (size_t)b * SEQ * DIM;
    __half* vdst = g_vth + (size_t)b * DIM * SEQ;
    const int x0 = blockIdx.x * 32;   // d
    const int y0 = blockIdx.y * 32;   // s
    const int tx = threadIdx.x & 31, ty = threadIdx.x >> 5;
#pragma unroll
    for (int j = 0; j < 4; j++)
        t[ty + j * 8][tx] = vsrc[(size_t)(y0 + ty + j * 8) * DIM + x0 + tx];
    __syncthreads();
#pragma unroll
    for (int j = 0; j < 4; j++)
        vdst[(size_t)(x0 + ty + j * 8) * SEQ + y0 + tx] = t[tx][ty + j * 8];
}

// ---------------------------------------------------------------------------
// Causal softmax: online (m,s) over fp32 scores, then recompute-normalize
// writing fp16 weights; zero-pad to 128 boundary.
// m is seeded with a FINITE lower bound (NEG_BIG): threads with empty ranges
// stay at NEG_BIG and merge as exp2f(finite-huge-negative)=0, never inf-inf.
// grid: (SEQ, BATCH)
// ---------------------------------------------------------------------------
__global__ __launch_bounds__(NTHR_S)
void softmax_kernel()
{
    const int j = blockIdx.x;
    const int b = blockIdx.y;
    const float* row = g_s + ((size_t)b * SEQ + j) * SEQ;
    __half* rowh = g_sh + ((size_t)b * SEQ + j) * SEQ;
    const int n = j + 1;
    const int n4 = n & ~3;

    __shared__ float rm[NTHR_S], rs[NTHR_S];
    const int tid = threadIdx.x;
    const float c2 = 0.03125f * 1.4426950408889634f;   // scale * log2(e)

    float m = NEG_BIG, s = 0.0f;
    for (int k = 4 * tid; k < n4; k += 4 * NTHR_S) {
        float4 v = *(const float4*)(row + k);
        float bm = fmaxf(fmaxf(v.x, v.y), fmaxf(v.z, v.w));
        if (bm > m) { s *= exp2f((m - bm) * c2); m = bm; }
        s += exp2f((v.x - m) * c2) + exp2f((v.y - m) * c2) +
             exp2f((v.z - m) * c2) + exp2f((v.w - m) * c2);
    }
    for (int k = n4 + tid; k < n; k += NTHR_S) {
        float v = row[k];
        if (v > m) { s *= exp2f((m - v) * c2); m = v; }
        s += exp2f((v - m) * c2);
    }
    rm[tid] = m; rs[tid] = s;
    __syncthreads();
    for (int st = NTHR_S / 2; st > 0; st >>= 1) {
        if (tid < st) {
            float m2 = rm[tid + st], s2 = rs[tid + st];
            float M = fmaxf(rm[tid], m2);
            rs[tid] = rs[tid] * exp2f((rm[tid] - M) * c2) + s2 * exp2f((m2 - M) * c2);
            rm[tid] = M;
        }
        __syncthreads();
    }
    const float M = rm[0];
    const float rsum = 1.0f / rs[0];

    // normalize pass: recompute exp, write fp16
    for (int k = 4 * tid; k < n4; k += 4 * NTHR_S) {
        float4 v = *(const float4*)(row + k);
        __half2 h0 = __floats2half2_rn(exp2f((v.x - M) * c2) * rsum,
                                       exp2f((v.y - M) * c2) * rsum);
        __half2 h1 = __floats2half2_rn(exp2f((v.z - M) * c2) * rsum,
                                       exp2f((v.w - M) * c2) * rsum);
        *(__half2*)(rowh + k)     = h0;
        *(__half2*)(rowh + k + 2) = h1;
    }
    for (int k = n4 + tid; k < n; k += NTHR_S)
        rowh[k] = __float2half_rn(exp2f((row[k] - M) * c2) * rsum);

    const int npad = ((j >> 7) + 1) << 7;
    for (int k = n + tid; k < npad; k += NTHR_S)
        rowh[k] = __ushort_as_half((unsigned short)0);
}

// ---------------------------------------------------------------------------
extern "C" void kernel_launch(void* const* d_in, const int* in_sizes, int n_in,
                              void* d_out, int out_size)
{
    const float* x  = (const float*)d_in[0];
    const float* Wq = (const float*)d_in[1];
    const float* bq = (const float*)d_in[2];
    const float* Wk = (const float*)d_in[3];
    const float* bk = (const float*)d_in[4];
    const float* Wv = (const float*)d_in[5];
    const float* bv = (const float*)d_in[6];
    float* out = (float*)d_out;

    cudaFuncSetAttribute(gemm_nt<0>, cudaFuncAttributeMaxDynamicSharedMemorySize, SMEM_BYTES);
    cudaFuncSetAttribute(gemm_nt<1>, cudaFuncAttributeMaxDynamicSharedMemorySize, SMEM_BYTES);
    cudaFuncSetAttribute(gemm_nt<2>, cudaFuncAttributeMaxDynamicSharedMemorySize, SMEM_BYTES);

    // prep
    conv_x_kernel<<<MTOT * DIM / (256 * 4), 256>>>(x);
    {
        dim3 g(DIM / 32, DIM / 32, 3);
        transpose_w_kernel<<<g, 256>>>(Wq, Wk, Wv);
    }
    // QKV
    {
        dim3 g(DIM / 128, MTOT / 128, 3);
        gemm_nt<0><<<g, NTHR_G, SMEM_BYTES>>>(nullptr, bq, bk, bv);
    }
    // v^T, scores
    {
        dim3 g(DIM / 32, SEQ / 32, BATCH);
        transpose_v_kernel<<<g, 256>>>();
    }
    {
        dim3 g(SEQ / 128, SEQ / 128, BATCH);
        gemm_nt<1><<<g, NTHR_G, SMEM_BYTES>>>(nullptr, nullptr, nullptr, nullptr);
    }
    // softmax
    {
        dim3 g(SEQ, BATCH);
        softmax_kernel<<<g, NTHR_S>>>();
    }
    // PV
    {
        dim3 g(DIM / 128, SEQ / 128, BATCH);
        gemm_nt<2><<<g, NTHR_G, SMEM_BYTES>>>(out, nullptr, nullptr, nullptr);
    }
}

// round 7
// speedup vs baseline: 7.9619x; 1.5000x over previous
#include <cuda_runtime.h>
#include <cuda_fp16.h>
#include <math.h>
#include <stdint.h>

// ---------------------------------------------------------------------------
// Problem constants
// ---------------------------------------------------------------------------
#define BATCH 4
#define SEQ   4096
#define DIM   1024
#define MTOT  (BATCH * SEQ)     // 16384

#define NTHR_G 256              // 8 warps per GEMM CTA (2x4 grid of 64x32 tiles)
#define NTHR_S 256
#define STAGES 3
#define BK     64               // halves per k-chunk (128 B per row)
#define TILE_B  16384           // 128 rows x 128 bytes
#define STAGE_B (2 * TILE_B)
#define SMEM_BYTES (STAGES * STAGE_B)   // 98304 (2 CTAs/SM: 192KB of 228KB)

#define NEG_BIG (-3.0e38f)      // finite -inf substitute (avoids inf-inf=nan)

// ---------------------------------------------------------------------------
// Scratch (__device__ globals: allocation-free rule)
// ---------------------------------------------------------------------------
__device__ __half g_xh[MTOT * DIM];                  // fp16 x
__device__ __half g_wth[3 * DIM * DIM];              // W^T fp16 (q,k,v)
__device__ __half g_qh[MTOT * DIM];
__device__ __half g_kh[MTOT * DIM];
__device__ __half g_vh[MTOT * DIM];
__device__ __half g_vth[(size_t)BATCH * DIM * SEQ];  // v^T fp16
__device__ float  g_s[(size_t)BATCH * SEQ * SEQ];    // raw scores fp32
__device__ __half g_sh[(size_t)BATCH * SEQ * SEQ];   // softmax weights fp16

// ---------------------------------------------------------------------------
// Helpers
// ---------------------------------------------------------------------------
__device__ __forceinline__ uint32_t smem_u32(const void* p) {
    return (uint32_t)__cvta_generic_to_shared(p);
}

__device__ __forceinline__ void cp16(uint32_t dst, const void* src) {
    asm volatile("cp.async.cg.shared.global [%0], [%1], 16;\n" :: "r"(dst), "l"(src));
}
#define CP_COMMIT() asm volatile("cp.async.commit_group;\n")
#define CP_WAIT1()  asm volatile("cp.async.wait_group 1;\n")
#define CP_WAIT0()  asm volatile("cp.async.wait_group 0;\n")

__device__ __forceinline__ void ldsm4(uint32_t* r, uint32_t addr) {
    asm volatile("ldmatrix.sync.aligned.m8n8.x4.shared.b16 {%0,%1,%2,%3}, [%4];"
                 : "=r"(r[0]), "=r"(r[1]), "=r"(r[2]), "=r"(r[3]) : "r"(addr));
}

__device__ __forceinline__ void mma16(float* d, const uint32_t* a, const uint32_t* b) {
    asm volatile(
        "mma.sync.aligned.m16n8k16.row.col.f32.f16.f16.f32 "
        "{%0,%1,%2,%3}, {%4,%5,%6,%7}, {%8,%9}, {%0,%1,%2,%3};\n"
        : "+f"(d[0]), "+f"(d[1]), "+f"(d[2]), "+f"(d[3])
        : "r"(a[0]), "r"(a[1]), "r"(a[2]), "r"(a[3]), "r"(b[0]), "r"(b[1]));
}

// ---------------------------------------------------------------------------
// Tile fill: 128 rows x 64 halves (128B/row), swizzled chunk = c16 ^ (r&7).
// 256 threads, 4 chunks each.
// ---------------------------------------------------------------------------
__device__ __forceinline__ void fill_tile(uint32_t sdst, const __half* __restrict__ g,
                                          int ld, int k0) {
    const int tid = threadIdx.x;
#pragma unroll
    for (int i = 0; i < 4; i++) {
        int c = tid + i * 256;
        int r = c >> 3, c16 = c & 7;
        cp16(sdst + r * 128 + ((c16 ^ (r & 7)) << 4),
             g + (size_t)r * ld + k0 + c16 * 8);
    }
}

// ---------------------------------------------------------------------------
// Unified NT fp16 GEMM: C[128x128] = A(row-major,K-contig) . B^T(K-contig rows)
// 8 warps (2x4 grid), warp tile 64x32, m16n8k16, 3-stage cp.async pipeline,
// ONE barrier per K-iter.
// MODE 0: QKV    A=g_xh,  B=g_wth[z], C=g_qh/g_kh/g_vh (+bias fp32, ->fp16)
// MODE 1: scores A=g_qh[z],B=g_kh[z], C=g_s (fp32), causal block skip
// MODE 2: PV     A=g_sh[z],B=g_vth[z],C=out (fp32),  K truncated at row0+128
// ---------------------------------------------------------------------------
template <int MODE>
__global__ __launch_bounds__(NTHR_G, 2)
void gemm_nt(float* __restrict__ Cout,
             const float* __restrict__ b0, const float* __restrict__ b1,
             const float* __restrict__ b2)
{
    const int row0 = blockIdx.y * 128;
    const int col0 = blockIdx.x * 128;
    const int z = blockIdx.z;
    if (MODE == 1 && col0 > row0) return;

    const __half *A, *B;
    const float* bias = nullptr;
    __half* Ch = nullptr;
    float* Cf = nullptr;
    int lda, ldb, ldc, nK;
    if (MODE == 0) {
        A = g_xh; lda = DIM;
        B = g_wth + (size_t)z * DIM * DIM; ldb = DIM;
        Ch = (z == 0 ? g_qh : (z == 1 ? g_kh : g_vh)); ldc = DIM;
        bias = (z == 0 ? b0 : (z == 1 ? b1 : b2));
        nK = DIM / BK;
    } else if (MODE == 1) {
        A = g_qh + (size_t)z * SEQ * DIM; lda = DIM;
        B = g_kh + (size_t)z * SEQ * DIM; ldb = DIM;
        Cf = g_s + (size_t)z * SEQ * SEQ; ldc = SEQ;
        nK = DIM / BK;
    } else {
        A = g_sh + (size_t)z * SEQ * SEQ; lda = SEQ;
        B = g_vth + (size_t)z * DIM * SEQ; ldb = SEQ;
        Cf = Cout + (size_t)z * SEQ * DIM; ldc = DIM;
        nK = (row0 + 128) / BK;
    }
    const __half* Arow = A + (size_t)row0 * lda;
    const __half* Brow = B + (size_t)col0 * ldb;

    extern __shared__ char smem[];
    const uint32_t sbase = smem_u32(smem);

    const int tid  = threadIdx.x;
    const int lane = tid & 31, warp = tid >> 5;
    const int wm = warp & 1, wn = warp >> 1;      // 2x4 warp grid: 64x32 tiles
    const int mat = lane >> 3, rl = lane & 7;     // ldmatrix address lanes

    float acc[4][4][4];
#pragma unroll
    for (int i = 0; i < 4; i++)
#pragma unroll
        for (int j = 0; j < 4; j++)
#pragma unroll
            for (int t = 0; t < 4; t++) acc[i][j][t] = 0.0f;

    // prologue: stages 0 and 1
    fill_tile(sbase, Arow, lda, 0);
    fill_tile(sbase + TILE_B, Brow, ldb, 0);
    CP_COMMIT();
    fill_tile(sbase + STAGE_B, Arow, lda, BK);
    fill_tile(sbase + STAGE_B + TILE_B, Brow, ldb, BK);
    CP_COMMIT();

    for (int it = 0; it < nK; ++it) {
        if (it + 1 < nK) { CP_WAIT1(); } else { CP_WAIT0(); }
        __syncthreads();
        // This barrier also proves all warps finished reading stage (it-1),
        // so prefetching into slot (it+2)%3 == (it-1)%3 is safe: one barrier/iter.
        if (it + 2 < nK) {
            const int slot = (it + 2) % STAGES;
            fill_tile(sbase + slot * STAGE_B, Arow, lda, (it + 2) * BK);
            fill_tile(sbase + slot * STAGE_B + TILE_B, Brow, ldb, (it + 2) * BK);
            CP_COMMIT();
        }

        const uint32_t sA = sbase + (it % STAGES) * STAGE_B;
        const uint32_t sB = sA + TILE_B;

#pragma unroll
        for (int kk = 0; kk < 4; kk++) {          // 4 x k16 per BK=64
            const int klo = kk * 2;               // 16B chunk index

            // A fragments: 4 m-tiles (64 rows)
            uint32_t a[4][4];
#pragma unroll
            for (int mt = 0; mt < 4; mt++) {
                int row = wm * 64 + mt * 16 + ((mat & 1) << 3) + rl;
                int c16 = klo + (mat >> 1);
                ldsm4(a[mt], sA + row * 128 + ((c16 ^ (row & 7)) << 4));
            }
            // B fragments: 4 n-tiles (32 cols), two per ldmatrix.x4
            uint32_t b[4][2];
#pragma unroll
            for (int t = 0; t < 2; t++) {
                int nrow = wn * 32 + t * 16 + ((mat >> 1) << 3) + rl;
                int c16 = klo + (mat & 1);
                uint32_t r4[4];
                ldsm4(r4, sB + nrow * 128 + ((c16 ^ (nrow & 7)) << 4));
                b[2 * t][0] = r4[0]; b[2 * t][1] = r4[1];
                b[2 * t + 1][0] = r4[2]; b[2 * t + 1][1] = r4[3];
            }
#pragma unroll
            for (int mt = 0; mt < 4; mt++)
#pragma unroll
                for (int nt = 0; nt < 4; nt++)
                    mma16(acc[mt][nt], a[mt], b[nt]);
        }
    }
    __syncthreads();   // protect nothing after, but keep epilogue ordered w/ loop exit

    // Epilogue
    const int gr0 = row0 + wm * 64 + (lane >> 2);
    const int gc0 = col0 + wn * 32 + (lane & 3) * 2;
#pragma unroll
    for (int mt = 0; mt < 4; mt++) {
#pragma unroll
        for (int nt = 0; nt < 4; nt++) {
            const int gr = gr0 + mt * 16;
            const int gc = gc0 + nt * 8;
            if (MODE == 0) {
                float2 bb = *(const float2*)(bias + gc);
                __half2 h0 = __floats2half2_rn(acc[mt][nt][0] + bb.x,
                                               acc[mt][nt][1] + bb.y);
                __half2 h1 = __floats2half2_rn(acc[mt][nt][2] + bb.x,
                                               acc[mt][nt][3] + bb.y);
                *(__half2*)(Ch + (size_t)gr * ldc + gc)       = h0;
                *(__half2*)(Ch + (size_t)(gr + 8) * ldc + gc) = h1;
            } else {
                *(float2*)(Cf + (size_t)gr * ldc + gc)       = *(float2*)&acc[mt][nt][0];
                *(float2*)(Cf + (size_t)(gr + 8) * ldc + gc) = *(float2*)&acc[mt][nt][2];
            }
        }
    }
}

// ---------------------------------------------------------------------------
// Prep kernels
// ---------------------------------------------------------------------------
__global__ __launch_bounds__(256)
void conv_x_kernel(const float* __restrict__ x)
{
    const int idx = blockIdx.x * 256 + threadIdx.x;   // one float4 each
    float4 v = *(const float4*)(x + (size_t)idx * 4);
    __half2* dst = (__half2*)(g_xh + (size_t)idx * 4);
    dst[0] = __floats2half2_rn(v.x, v.y);
    dst[1] = __floats2half2_rn(v.z, v.w);
}

__global__ __launch_bounds__(256)
void transpose_w_kernel(const float* __restrict__ Wq, const float* __restrict__ Wk,
                        const float* __restrict__ Wv)
{
    __shared__ float t[32][33];
    const int zz = blockIdx.z;
    const float* W = (zz == 0 ? Wq : (zz == 1 ? Wk : Wv));
    const int x0 = blockIdx.x * 32;   // n
    const int y0 = blockIdx.y * 32;   // k
    const int tx = threadIdx.x & 31, ty = threadIdx.x >> 5;
#pragma unroll
    for (int j = 0; j < 4; j++)
        t[ty + j * 8][tx] = W[(size_t)(y0 + ty + j * 8) * DIM + x0 + tx];
    __syncthreads();
    __half* out = g_wth + (size_t)zz * DIM * DIM;
#pragma unroll
    for (int j = 0; j < 4; j++)
        out[(size_t)(x0 + ty + j * 8) * DIM + y0 + tx] = __float2half_rn(t[tx][ty + j * 8]);
}

__global__ __launch_bounds__(256)
void transpose_v_kernel()
{
    __shared__ __half t[32][34];
    const int b = blockIdx.z;
    const __half* vsrc = g_vh + (size_t)b * SEQ * DIM;
    __half* vdst = g_vth + (size_t)b * DIM * SEQ;
    const int x0 = blockIdx.x * 32;   // d
    const int y0 = blockIdx.y * 32;   // s
    const int tx = threadIdx.x & 31, ty = threadIdx.x >> 5;
#pragma unroll
    for (int j = 0; j < 4; j++)
        t[ty + j * 8][tx] = vsrc[(size_t)(y0 + ty + j * 8) * DIM + x0 + tx];
    __syncthreads();
#pragma unroll
    for (int j = 0; j < 4; j++)
        vdst[(size_t)(x0 + ty + j * 8) * SEQ + y0 + tx] = t[tx][ty + j * 8];
}

// ---------------------------------------------------------------------------
// Causal softmax: online (m,s) over fp32 scores, then recompute-normalize
// writing fp16 weights; zero-pad to 128 boundary. m seeded with finite
// NEG_BIG so empty-range threads never produce inf-inf=nan in merges.
// grid: (SEQ, BATCH)
// ---------------------------------------------------------------------------
__global__ __launch_bounds__(NTHR_S)
void softmax_kernel()
{
    const int j = blockIdx.x;
    const int b = blockIdx.y;
    const float* row = g_s + ((size_t)b * SEQ + j) * SEQ;
    __half* rowh = g_sh + ((size_t)b * SEQ + j) * SEQ;
    const int n = j + 1;
    const int n4 = n & ~3;

    __shared__ float rm[NTHR_S], rs[NTHR_S];
    const int tid = threadIdx.x;
    const float c2 = 0.03125f * 1.4426950408889634f;   // scale * log2(e)

    float m = NEG_BIG, s = 0.0f;
    for (int k = 4 * tid; k < n4; k += 4 * NTHR_S) {
        float4 v = *(const float4*)(row + k);
        float bm = fmaxf(fmaxf(v.x, v.y), fmaxf(v.z, v.w));
        if (bm > m) { s *= exp2f((m - bm) * c2); m = bm; }
        s += exp2f((v.x - m) * c2) + exp2f((v.y - m) * c2) +
             exp2f((v.z - m) * c2) + exp2f((v.w - m) * c2);
    }
    for (int k = n4 + tid; k < n; k += NTHR_S) {
        float v = row[k];
        if (v > m) { s *= exp2f((m - v) * c2); m = v; }
        s += exp2f((v - m) * c2);
    }
    rm[tid] = m; rs[tid] = s;
    __syncthreads();
    for (int st = NTHR_S / 2; st > 0; st >>= 1) {
        if (tid < st) {
            float m2 = rm[tid + st], s2 = rs[tid + st];
            float M = fmaxf(rm[tid], m2);
            rs[tid] = rs[tid] * exp2f((rm[tid] - M) * c2) + s2 * exp2f((m2 - M) * c2);
            rm[tid] = M;
        }
        __syncthreads();
    }
    const float M = rm[0];
    const float rsum = 1.0f / rs[0];

    for (int k = 4 * tid; k < n4; k += 4 * NTHR_S) {
        float4 v = *(const float4*)(row + k);
        __half2 h0 = __floats2half2_rn(exp2f((v.x - M) * c2) * rsum,
                                       exp2f((v.y - M) * c2) * rsum);
        __half2 h1 = __floats2half2_rn(exp2f((v.z - M) * c2) * rsum,
                                       exp2f((v.w - M) * c2) * rsum);
        *(__half2*)(rowh + k)     = h0;
        *(__half2*)(rowh + k + 2) = h1;
    }
    for (int k = n4 + tid; k < n; k += NTHR_S)
        rowh[k] = __float2half_rn(exp2f((row[k] - M) * c2) * rsum);

    const int npad = ((j >> 7) + 1) << 7;
    for (int k = n + tid; k < npad; k += NTHR_S)
        rowh[k] = __ushort_as_half((unsigned short)0);
}

// ---------------------------------------------------------------------------
extern "C" void kernel_launch(void* const* d_in, const int* in_sizes, int n_in,
                              void* d_out, int out_size)
{
    const float* x  = (const float*)d_in[0];
    const float* Wq = (const float*)d_in[1];
    const float* bq = (const float*)d_in[2];
    const float* Wk = (const float*)d_in[3];
    const float* bk = (const float*)d_in[4];
    const float* Wv = (const float*)d_in[5];
    const float* bv = (const float*)d_in[6];
    float* out = (float*)d_out;

    cudaFuncSetAttribute(gemm_nt<0>, cudaFuncAttributeMaxDynamicSharedMemorySize, SMEM_BYTES);
    cudaFuncSetAttribute(gemm_nt<1>, cudaFuncAttributeMaxDynamicSharedMemorySize, SMEM_BYTES);
    cudaFuncSetAttribute(gemm_nt<2>, cudaFuncAttributeMaxDynamicSharedMemorySize, SMEM_BYTES);

    // prep
    conv_x_kernel<<<MTOT * DIM / (256 * 4), 256>>>(x);
    {
        dim3 g(DIM / 32, DIM / 32, 3);
        transpose_w_kernel<<<g, 256>>>(Wq, Wk, Wv);
    }
    // QKV
    {
        dim3 g(DIM / 128, MTOT / 128, 3);
        gemm_nt<0><<<g, NTHR_G, SMEM_BYTES>>>(nullptr, bq, bk, bv);
    }
    // v^T, scores
    {
        dim3 g(DIM / 32, SEQ / 32, BATCH);
        transpose_v_kernel<<<g, 256>>>();
    }
    {
        dim3 g(SEQ / 128, SEQ / 128, BATCH);
        gemm_nt<1><<<g, NTHR_G, SMEM_BYTES>>>(nullptr, nullptr, nullptr, nullptr);
    }
    // softmax
    {
        dim3 g(SEQ, BATCH);
        softmax_kernel<<<g, NTHR_S>>>();
    }
    // PV
    {
        dim3 g(DIM / 128, SEQ / 128, BATCH);
        gemm_nt<2><<<g, NTHR_G, SMEM_BYTES>>>(out, nullptr, nullptr, nullptr);
    }
}

// round 8
// speedup vs baseline: 8.5702x; 1.0764x over previous
#include <cuda_runtime.h>
#include <cuda_fp16.h>
#include <math.h>
#include <stdint.h>

// ---------------------------------------------------------------------------
// Problem constants
// ---------------------------------------------------------------------------
#define BATCH 4
#define SEQ   4096
#define DIM   1024
#define MTOT  (BATCH * SEQ)     // 16384

#define NTHR_G 256              // 8 warps per GEMM CTA (2x4 grid of 64x32 tiles)
#define STAGES 3
#define BK     64               // halves per k-chunk (128 B per row)
#define TILE_B  16384           // 128 rows x 128 bytes
#define STAGE_B (2 * TILE_B)
#define SMEM_BYTES (STAGES * STAGE_B)   // 98304 (2 CTAs/SM)

// ---------------------------------------------------------------------------
// Scratch (__device__ globals: allocation-free rule)
// ---------------------------------------------------------------------------
__device__ __half g_xh[MTOT * DIM];                  // fp16 x
__device__ __half g_wth[3 * DIM * DIM];              // W^T fp16 (q,k,v)
__device__ __half g_qh[MTOT * DIM];
__device__ __half g_kh[MTOT * DIM];
__device__ __half g_vh[MTOT * DIM];
__device__ __half g_vth[(size_t)BATCH * DIM * SEQ];  // v^T fp16
__device__ __half g_sh[(size_t)BATCH * SEQ * SEQ];   // UNNORMALIZED exp weights fp16
__device__ float  g_l[MTOT];                         // per-row weight sums

// ---------------------------------------------------------------------------
// Helpers
// ---------------------------------------------------------------------------
__device__ __forceinline__ uint32_t smem_u32(const void* p) {
    return (uint32_t)__cvta_generic_to_shared(p);
}

__device__ __forceinline__ void cp16(uint32_t dst, const void* src) {
    asm volatile("cp.async.cg.shared.global [%0], [%1], 16;\n" :: "r"(dst), "l"(src));
}
#define CP_COMMIT() asm volatile("cp.async.commit_group;\n")
#define CP_WAIT1()  asm volatile("cp.async.wait_group 1;\n")
#define CP_WAIT0()  asm volatile("cp.async.wait_group 0;\n")

__device__ __forceinline__ void ldsm4(uint32_t* r, uint32_t addr) {
    asm volatile("ldmatrix.sync.aligned.m8n8.x4.shared.b16 {%0,%1,%2,%3}, [%4];"
                 : "=r"(r[0]), "=r"(r[1]), "=r"(r[2]), "=r"(r[3]) : "r"(addr));
}

__device__ __forceinline__ void mma16(float* d, const uint32_t* a, const uint32_t* b) {
    asm volatile(
        "mma.sync.aligned.m16n8k16.row.col.f32.f16.f16.f32 "
        "{%0,%1,%2,%3}, {%4,%5,%6,%7}, {%8,%9}, {%0,%1,%2,%3};\n"
        : "+f"(d[0]), "+f"(d[1]), "+f"(d[2]), "+f"(d[3])
        : "r"(a[0]), "r"(a[1]), "r"(a[2]), "r"(a[3]), "r"(b[0]), "r"(b[1]));
}

// exp2 with clamp: keeps fp16 finite even for pathological scores
__device__ __forceinline__ float wexp(float s, float c2) {
    return exp2f(fminf(s * c2, 15.0f));
}

// ---------------------------------------------------------------------------
// Tile fill: 128 rows x 64 halves (128B/row), swizzled chunk = c16 ^ (r&7).
// 256 threads, 4 chunks each.
// ---------------------------------------------------------------------------
__device__ __forceinline__ void fill_tile(uint32_t sdst, const __half* __restrict__ g,
                                          int ld, int k0) {
    const int tid = threadIdx.x;
#pragma unroll
    for (int i = 0; i < 4; i++) {
        int c = tid + i * 256;
        int r = c >> 3, c16 = c & 7;
        cp16(sdst + r * 128 + ((c16 ^ (r & 7)) << 4),
             g + (size_t)r * ld + k0 + c16 * 8);
    }
}

// ---------------------------------------------------------------------------
// Unified NT fp16 GEMM: C[128x128] = A(row-major,K-contig) . B^T(K-contig rows)
// 8 warps (2x4 grid), warp tile 64x32, m16n8k16, 3-stage cp.async pipeline,
// one barrier per K-iter.
// MODE 0: QKV    A=g_xh,  B=g_wth[z], C=g_qh/g_kh/g_vh (+bias fp32, ->fp16)
// MODE 1: scores A=g_qh[z],B=g_kh[z], C=g_sh: w = exp2(s*c2) fp16, causal mask
// MODE 2: PV     A=g_sh[z],B=g_vth[z],C=out fp32 scaled by 1/g_l[row]
// ---------------------------------------------------------------------------
template <int MODE>
__global__ __launch_bounds__(NTHR_G, 2)
void gemm_nt(float* __restrict__ Cout,
             const float* __restrict__ b0, const float* __restrict__ b1,
             const float* __restrict__ b2)
{
    const int row0 = blockIdx.y * 128;
    const int col0 = blockIdx.x * 128;
    const int z = blockIdx.z;
    if (MODE == 1 && col0 > row0) return;

    const __half *A, *B;
    const float* bias = nullptr;
    __half* Ch = nullptr;
    float* Cf = nullptr;
    int lda, ldb, ldc, nK;
    if (MODE == 0) {
        A = g_xh; lda = DIM;
        B = g_wth + (size_t)z * DIM * DIM; ldb = DIM;
        Ch = (z == 0 ? g_qh : (z == 1 ? g_kh : g_vh)); ldc = DIM;
        bias = (z == 0 ? b0 : (z == 1 ? b1 : b2));
        nK = DIM / BK;
    } else if (MODE == 1) {
        A = g_qh + (size_t)z * SEQ * DIM; lda = DIM;
        B = g_kh + (size_t)z * SEQ * DIM; ldb = DIM;
        Ch = g_sh + (size_t)z * SEQ * SEQ; ldc = SEQ;
        nK = DIM / BK;
    } else {
        A = g_sh + (size_t)z * SEQ * SEQ; lda = SEQ;
        B = g_vth + (size_t)z * DIM * SEQ; ldb = SEQ;
        Cf = Cout + (size_t)z * SEQ * DIM; ldc = DIM;
        nK = (row0 + 128) / BK;
    }
    const __half* Arow = A + (size_t)row0 * lda;
    const __half* Brow = B + (size_t)col0 * ldb;

    extern __shared__ char smem[];
    const uint32_t sbase = smem_u32(smem);

    const int tid  = threadIdx.x;
    const int lane = tid & 31, warp = tid >> 5;
    const int wm = warp & 1, wn = warp >> 1;      // 2x4 warp grid: 64x32 tiles
    const int mat = lane >> 3, rl = lane & 7;     // ldmatrix address lanes

    float acc[4][4][4];
#pragma unroll
    for (int i = 0; i < 4; i++)
#pragma unroll
        for (int j = 0; j < 4; j++)
#pragma unroll
            for (int t = 0; t < 4; t++) acc[i][j][t] = 0.0f;

    // prologue: stages 0 and 1
    fill_tile(sbase, Arow, lda, 0);
    fill_tile(sbase + TILE_B, Brow, ldb, 0);
    CP_COMMIT();
    fill_tile(sbase + STAGE_B, Arow, lda, BK);
    fill_tile(sbase + STAGE_B + TILE_B, Brow, ldb, BK);
    CP_COMMIT();

    for (int it = 0; it < nK; ++it) {
        if (it + 1 < nK) { CP_WAIT1(); } else { CP_WAIT0(); }
        __syncthreads();
        // This barrier proves all warps finished reading stage (it-1),
        // so prefetching into slot (it+2)%3 == (it-1)%3 is safe: one barrier/iter.
        if (it + 2 < nK) {
            const int slot = (it + 2) % STAGES;
            fill_tile(sbase + slot * STAGE_B, Arow, lda, (it + 2) * BK);
            fill_tile(sbase + slot * STAGE_B + TILE_B, Brow, ldb, (it + 2) * BK);
            CP_COMMIT();
        }

        const uint32_t sA = sbase + (it % STAGES) * STAGE_B;
        const uint32_t sB = sA + TILE_B;

#pragma unroll
        for (int kk = 0; kk < 4; kk++) {          // 4 x k16 per BK=64
            const int klo = kk * 2;               // 16B chunk index

            uint32_t a[4][4];
#pragma unroll
            for (int mt = 0; mt < 4; mt++) {
                int row = wm * 64 + mt * 16 + ((mat & 1) << 3) + rl;
                int c16 = klo + (mat >> 1);
                ldsm4(a[mt], sA + row * 128 + ((c16 ^ (row & 7)) << 4));
            }
            uint32_t b[4][2];
#pragma unroll
            for (int t = 0; t < 2; t++) {
                int nrow = wn * 32 + t * 16 + ((mat >> 1) << 3) + rl;
                int c16 = klo + (mat & 1);
                uint32_t r4[4];
                ldsm4(r4, sB + nrow * 128 + ((c16 ^ (nrow & 7)) << 4));
                b[2 * t][0] = r4[0]; b[2 * t][1] = r4[1];
                b[2 * t + 1][0] = r4[2]; b[2 * t + 1][1] = r4[3];
            }
#pragma unroll
            for (int mt = 0; mt < 4; mt++)
#pragma unroll
                for (int nt = 0; nt < 4; nt++)
                    mma16(acc[mt][nt], a[mt], b[nt]);
        }
    }

    // Epilogue
    const int gr0 = row0 + wm * 64 + (lane >> 2);
    const int gc0 = col0 + wn * 32 + (lane & 3) * 2;
    const float c2 = 0.03125f * 1.4426950408889634f;   // (1/sqrt(1024)) * log2(e)
    const bool diag = (MODE == 1) && (col0 == row0);

#pragma unroll
    for (int mt = 0; mt < 4; mt++) {
        const int gr = gr0 + mt * 16;
        float inv0 = 1.0f, inv1 = 1.0f;
        if (MODE == 2) {
            inv0 = 1.0f / g_l[(size_t)z * SEQ + gr];
            inv1 = 1.0f / g_l[(size_t)z * SEQ + gr + 8];
        }
#pragma unroll
        for (int nt = 0; nt < 4; nt++) {
            const int gc = gc0 + nt * 8;
            if (MODE == 0) {
                float2 bb = *(const float2*)(bias + gc);
                __half2 h0 = __floats2half2_rn(acc[mt][nt][0] + bb.x,
                                               acc[mt][nt][1] + bb.y);
                __half2 h1 = __floats2half2_rn(acc[mt][nt][2] + bb.x,
                                               acc[mt][nt][3] + bb.y);
                *(__half2*)(Ch + (size_t)gr * ldc + gc)       = h0;
                *(__half2*)(Ch + (size_t)(gr + 8) * ldc + gc) = h1;
            } else if (MODE == 1) {
                float w0 = wexp(acc[mt][nt][0], c2);
                float w1 = wexp(acc[mt][nt][1], c2);
                float w2 = wexp(acc[mt][nt][2], c2);
                float w3 = wexp(acc[mt][nt][3], c2);
                if (diag) {
                    if (gc > gr)         w0 = 0.0f;
                    if (gc + 1 > gr)     w1 = 0.0f;
                    if (gc > gr + 8)     w2 = 0.0f;
                    if (gc + 1 > gr + 8) w3 = 0.0f;
                }
                *(__half2*)(Ch + (size_t)gr * ldc + gc)       = __floats2half2_rn(w0, w1);
                *(__half2*)(Ch + (size_t)(gr + 8) * ldc + gc) = __floats2half2_rn(w2, w3);
            } else {
                float2 o0, o1;
                o0.x = acc[mt][nt][0] * inv0;
                o0.y = acc[mt][nt][1] * inv0;
                o1.x = acc[mt][nt][2] * inv1;
                o1.y = acc[mt][nt][3] * inv1;
                *(float2*)(Cf + (size_t)gr * ldc + gc)       = o0;
                *(float2*)(Cf + (size_t)(gr + 8) * ldc + gc) = o1;
            }
        }
    }
}

// ---------------------------------------------------------------------------
// Prep kernels
// ---------------------------------------------------------------------------
__global__ __launch_bounds__(256)
void conv_x_kernel(const float* __restrict__ x)
{
    const int idx = blockIdx.x * 256 + threadIdx.x;   // one float4 each
    float4 v = *(const float4*)(x + (size_t)idx * 4);
    __half2* dst = (__half2*)(g_xh + (size_t)idx * 4);
    dst[0] = __floats2half2_rn(v.x, v.y);
    dst[1] = __floats2half2_rn(v.z, v.w);
}

__global__ __launch_bounds__(256)
void transpose_w_kernel(const float* __restrict__ Wq, const float* __restrict__ Wk,
                        const float* __restrict__ Wv)
{
    __shared__ float t[32][33];
    const int zz = blockIdx.z;
    const float* W = (zz == 0 ? Wq : (zz == 1 ? Wk : Wv));
    const int x0 = blockIdx.x * 32;   // n
    const int y0 = blockIdx.y * 32;   // k
    const int tx = threadIdx.x & 31, ty = threadIdx.x >> 5;
#pragma unroll
    for (int j = 0; j < 4; j++)
        t[ty + j * 8][tx] = W[(size_t)(y0 + ty + j * 8) * DIM + x0 + tx];
    __syncthreads();
    __half* out = g_wth + (size_t)zz * DIM * DIM;
#pragma unroll
    for (int j = 0; j < 4; j++)
        out[(size_t)(x0 + ty + j * 8) * DIM + y0 + tx] = __float2half_rn(t[tx][ty + j * 8]);
}

__global__ __launch_bounds__(256)
void transpose_v_kernel()
{
    __shared__ __half t[32][34];
    const int b = blockIdx.z;
    const __half* vsrc = g_vh + (size_t)b * SEQ * DIM;
    __half* vdst = g_vth + (size_t)b * DIM * SEQ;
    const int x0 = blockIdx.x * 32;   // d
    const int y0 = blockIdx.y * 32;   // s
    const int tx = threadIdx.x & 31, ty = threadIdx.x >> 5;
#pragma unroll
    for (int j = 0; j < 4; j++)
        t[ty + j * 8][tx] = vsrc[(size_t)(y0 + ty + j * 8) * DIM + x0 + tx];
    __syncthreads();
#pragma unroll
    for (int j = 0; j < 4; j++)
        vdst[(size_t)(x0 + ty + j * 8) * SEQ + y0 + tx] = t[tx][ty + j * 8];
}

// ---------------------------------------------------------------------------
// Row sums of the unnormalized fp16 weights: l[row] = sum_{k<=row} w[row][k].
// grid: (SEQ, BATCH), 128 threads.
// ---------------------------------------------------------------------------
__global__ __launch_bounds__(128)
void rowsum_kernel()
{
    const int j = blockIdx.x;
    const int b = blockIdx.y;
    const __half* row = g_sh + ((size_t)b * SEQ + j) * SEQ;
    const int n = j + 1;
    const int n8 = n & ~7;

    __shared__ float red[128];
    const int tid = threadIdx.x;

    float s = 0.0f;
    for (int k = 8 * tid; k < n8; k += 8 * 128) {
        float4 v4 = *(const float4*)(row + k);      // 8 halves
        const __half2* h = (const __half2*)&v4;
#pragma unroll
        for (int t = 0; t < 4; t++) {
            float2 f = __half22float2(h[t]);
            s += f.x + f.y;
        }
    }
    for (int k = n8 + tid; k < n; k += 128)
        s += __half2float(row[k]);

    red[tid] = s;
    __syncthreads();
    for (int st = 64; st > 0; st >>= 1) {
        if (tid < st) red[tid] += red[tid + st];
        __syncthreads();
    }
    if (tid == 0) g_l[b * SEQ + j] = red[0];
}

// ---------------------------------------------------------------------------
extern "C" void kernel_launch(void* const* d_in, const int* in_sizes, int n_in,
                              void* d_out, int out_size)
{
    const float* x  = (const float*)d_in[0];
    const float* Wq = (const float*)d_in[1];
    const float* bq = (const float*)d_in[2];
    const float* Wk = (const float*)d_in[3];
    const float* bk = (const float*)d_in[4];
    const float* Wv = (const float*)d_in[5];
    const float* bv = (const float*)d_in[6];
    float* out = (float*)d_out;

    cudaFuncSetAttribute(gemm_nt<0>, cudaFuncAttributeMaxDynamicSharedMemorySize, SMEM_BYTES);
    cudaFuncSetAttribute(gemm_nt<1>, cudaFuncAttributeMaxDynamicSharedMemorySize, SMEM_BYTES);
    cudaFuncSetAttribute(gemm_nt<2>, cudaFuncAttributeMaxDynamicSharedMemorySize, SMEM_BYTES);

    // prep
    conv_x_kernel<<<MTOT * DIM / (256 * 4), 256>>>(x);
    {
        dim3 g(DIM / 32, DIM / 32, 3);
        transpose_w_kernel<<<g, 256>>>(Wq, Wk, Wv);
    }
    // QKV
    {
        dim3 g(DIM / 128, MTOT / 128, 3);
        gemm_nt<0><<<g, NTHR_G, SMEM_BYTES>>>(nullptr, bq, bk, bv);
    }
    // v^T
    {
        dim3 g(DIM / 32, SEQ / 32, BATCH);
        transpose_v_kernel<<<g, 256>>>();
    }
    // scores -> unnormalized exp weights (fp16) with causal mask
    {
        dim3 g(SEQ / 128, SEQ / 128, BATCH);
        gemm_nt<1><<<g, NTHR_G, SMEM_BYTES>>>(nullptr, nullptr, nullptr, nullptr);
    }
    // row sums
    {
        dim3 g(SEQ, BATCH);
        rowsum_kernel<<<g, 128>>>();
    }
    // PV with 1/l scaling in epilogue
    {
        dim3 g(DIM / 128, SEQ / 128, BATCH);
        gemm_nt<2><<<g, NTHR_G, SMEM_BYTES>>>(out, nullptr, nullptr, nullptr);
    }
}